// round 4
// baseline (speedup 1.0000x reference)
#include <cuda_runtime.h>
#include <cuda_bf16.h>
#include <cstdint>
#include <math.h>

#define BB 4
#define SS 2048
#define DD 2048
typedef __nv_bfloat16 bf16;

#define XROWS (BB * SS)           // 8192

// ---------------- scratch (static device globals; no allocs) ----------------
__device__ int8_t g_x1[(size_t)XROWS*DD], g_x2[(size_t)XROWS*DD];
__device__ float  g_sx[XROWS];
__device__ int8_t g_W1T[3][(size_t)DD*DD], g_W2T[3][(size_t)DD*DD];
__device__ float  g_sW[3*DD];
__device__ float  g_cpart[16*DD];
__device__ float  g_QKV[3][(size_t)BB*SS*DD];
__device__ int8_t g_Q1[(size_t)XROWS*DD], g_Q2[(size_t)XROWS*DD];
__device__ int8_t g_K1[(size_t)XROWS*DD], g_K2[(size_t)XROWS*DD];
__device__ float  g_sQ[XROWS], g_sK[XROWS];
__device__ bf16   g_Vthi[(size_t)BB*SS*DD], g_Vtlo[(size_t)BB*SS*DD];
__device__ float  g_P[(size_t)BB*SS*SS];
__device__ bf16   g_Phi[(size_t)BB*SS*SS], g_Plo[(size_t)BB*SS*SS];

// ---------------- helpers ----------------
__device__ __forceinline__ uint32_t smem_u32(const void* p) {
    uint32_t a;
    asm("{ .reg .u64 t; cvta.to.shared.u64 t, %1; cvt.u32.u64 %0, t; }" : "=r"(a) : "l"(p));
    return a;
}
__device__ __forceinline__ void cp16(uint32_t dst, const void* src) {
    asm volatile("cp.async.cg.shared.global [%0], [%1], 16;" :: "r"(dst), "l"(src));
}
__device__ __forceinline__ void ldm4(uint32_t r[4], uint32_t addr) {
    asm volatile("ldmatrix.sync.aligned.m8n8.x4.shared.b16 {%0,%1,%2,%3}, [%4];"
                 : "=r"(r[0]), "=r"(r[1]), "=r"(r[2]), "=r"(r[3]) : "r"(addr));
}
__device__ __forceinline__ void mma_bf16(float c[4], const uint32_t a[4], const uint32_t b[2]) {
    asm volatile(
        "mma.sync.aligned.m16n8k16.row.col.f32.bf16.bf16.f32 "
        "{%0,%1,%2,%3}, {%4,%5,%6,%7}, {%8,%9}, {%0,%1,%2,%3};"
        : "+f"(c[0]), "+f"(c[1]), "+f"(c[2]), "+f"(c[3])
        : "r"(a[0]), "r"(a[1]), "r"(a[2]), "r"(a[3]), "r"(b[0]), "r"(b[1]));
}
__device__ __forceinline__ void mma_s8(int c[4], const uint32_t a[4], uint32_t b0, uint32_t b1) {
    asm volatile(
        "mma.sync.aligned.m16n8k32.row.col.s32.s8.s8.s32 "
        "{%0,%1,%2,%3}, {%4,%5,%6,%7}, {%8,%9}, {%0,%1,%2,%3};"
        : "+r"(c[0]), "+r"(c[1]), "+r"(c[2]), "+r"(c[3])
        : "r"(a[0]), "r"(a[1]), "r"(a[2]), "r"(a[3]), "r"(b0), "r"(b1));
}
__device__ __forceinline__ uint32_t pack2(bf16 a, bf16 b) {
    return (uint32_t)__bfloat16_as_ushort(a) | ((uint32_t)__bfloat16_as_ushort(b) << 16);
}
__device__ __forceinline__ int clamp127(int v) {
    return v > 127 ? 127 : (v < -127 ? -127 : v);
}

// shared smem geometry (both GEMM kernels): 4 arrays of 128 rows x 64B (+16B pad)
#define RSTRIDE 80
#define ARR_BYTES (128 * RSTRIDE)        // 10240
#define STAGE_BYTES (4 * ARR_BYTES)      // 40960
#define NSTAGE 4
#define SMEM_GEMM (NSTAGE * STAGE_BYTES) // 163840

// ============================================================================
// int8 two-level GEMM: C[z] = alpha * sA[m]*sB[n]*(A1B1 + (A1B2+A2B1)/256)
// A: [M,K] s8 rows; B: [N,K] s8 rows. K per iter = 64 bytes. fp32 out.
// MODE 0: dense.  MODE 1: skip tiles fully above causal diagonal.
// ============================================================================
template<int MODE>
__global__ void __launch_bounds__(256, 1)
gemm_s8(const int8_t* __restrict__ A1g, const int8_t* __restrict__ A2g,
        const int8_t* __restrict__ B1g, const int8_t* __restrict__ B2g,
        const float* __restrict__ sA, const float* __restrict__ sB,
        float* __restrict__ Cf,
        int M, int N, int K,
        size_t strA, size_t strB, size_t strC, size_t strSA, size_t strSB,
        float alpha)
{
    const int m0 = blockIdx.y * 128;
    const int n0 = blockIdx.x * 128;
    const int z  = blockIdx.z;
    if (MODE == 1 && n0 > m0) return;
    const int KT = K / 64;

    extern __shared__ char smem[];
    const uint32_t sbase = smem_u32(smem);
    const int tid  = threadIdx.x;
    const int lane = tid & 31;
    const int wid  = tid >> 5;
    const int wm   = (wid >> 2) * 64;
    const int wn   = (wid & 3) * 32;

    const int8_t* pA1 = A1g + (size_t)z * strA;
    const int8_t* pA2 = A2g + (size_t)z * strA;
    const int8_t* pB1 = B1g + (size_t)z * strB;
    const int8_t* pB2 = B2g + (size_t)z * strB;

    const int lr = tid >> 2;
    const int sg = tid & 3;

    auto load_stage = [&](int s, int kt) {
        if (kt < KT) {
            const uint32_t st = sbase + (uint32_t)s * STAGE_BYTES;
            const size_t ko = (size_t)kt * 64 + sg * 16;
            const uint32_t so = (uint32_t)(lr * RSTRIDE + sg * 16);
            cp16(st + 0*ARR_BYTES + so,              pA1 + (size_t)(m0 + lr) * K + ko);
            cp16(st + 0*ARR_BYTES + so + 64*RSTRIDE, pA1 + (size_t)(m0 + lr + 64) * K + ko);
            cp16(st + 1*ARR_BYTES + so,              pA2 + (size_t)(m0 + lr) * K + ko);
            cp16(st + 1*ARR_BYTES + so + 64*RSTRIDE, pA2 + (size_t)(m0 + lr + 64) * K + ko);
            cp16(st + 2*ARR_BYTES + so,              pB1 + (size_t)(n0 + lr) * K + ko);
            cp16(st + 2*ARR_BYTES + so + 64*RSTRIDE, pB1 + (size_t)(n0 + lr + 64) * K + ko);
            cp16(st + 3*ARR_BYTES + so,              pB2 + (size_t)(n0 + lr) * K + ko);
            cp16(st + 3*ARR_BYTES + so + 64*RSTRIDE, pB2 + (size_t)(n0 + lr + 64) * K + ko);
        }
        asm volatile("cp.async.commit_group;" ::: "memory");
    };

    const int arow = lane & 15;
    const int akh  = lane >> 4;
    const int nrow = (lane & 7) + ((lane >> 4) << 3);
    const int bkh  = (lane >> 3) & 1;
    const uint32_t aoff = (uint32_t)((wm + arow) * RSTRIDE + akh * 16);
    const uint32_t boff = (uint32_t)((wn + nrow) * RSTRIDE + bkh * 16);

    int acc1[4][4][4], acc2[4][4][4];
#pragma unroll
    for (int i = 0; i < 4; i++)
#pragma unroll
        for (int j = 0; j < 4; j++)
#pragma unroll
            for (int q = 0; q < 4; q++) { acc1[i][j][q] = 0; acc2[i][j][q] = 0; }

    load_stage(0, 0);
    load_stage(1, 1);
    load_stage(2, 2);

    for (int it = 0; it < KT; it++) {
        const int s = it & (NSTAGE - 1);
        asm volatile("cp.async.wait_group 2;" ::: "memory");
        __syncthreads();
        const uint32_t stg = sbase + (uint32_t)s * STAGE_BYTES;
#pragma unroll
        for (int ks = 0; ks < 2; ks++) {
            uint32_t a1[4][4], a2[4][4];
#pragma unroll
            for (int mt = 0; mt < 4; mt++) {
                ldm4(a1[mt], stg + 0*ARR_BYTES + aoff + mt * (16 * RSTRIDE) + ks * 32);
                ldm4(a2[mt], stg + 1*ARR_BYTES + aoff + mt * (16 * RSTRIDE) + ks * 32);
            }
#pragma unroll
            for (int ntp = 0; ntp < 2; ntp++) {
                uint32_t tb1[4], tb2[4];
                ldm4(tb1, stg + 2*ARR_BYTES + boff + ntp * (16 * RSTRIDE) + ks * 32);
                ldm4(tb2, stg + 3*ARR_BYTES + boff + ntp * (16 * RSTRIDE) + ks * 32);
#pragma unroll
                for (int mt = 0; mt < 4; mt++) {
#pragma unroll
                    for (int h = 0; h < 2; h++) {
                        const int nt = 2 * ntp + h;
                        mma_s8(acc1[mt][nt], a1[mt], tb1[2*h], tb1[2*h+1]);
                        mma_s8(acc2[mt][nt], a1[mt], tb2[2*h], tb2[2*h+1]);
                        mma_s8(acc2[mt][nt], a2[mt], tb1[2*h], tb1[2*h+1]);
                    }
                }
            }
        }
        load_stage((it + 3) & (NSTAGE - 1), it + 3);
    }

    // ---- epilogue ----
    const int r0 = wm + (lane >> 2);
    const int c0 = wn + (lane & 3) * 2;
    const float* sAp = sA + (size_t)z * strSA;
    const float* sBp = sB + (size_t)z * strSB;
#pragma unroll
    for (int mt = 0; mt < 4; mt++) {
        const int row = m0 + r0 + mt * 16;
        const float sa0 = sAp[row] * alpha;
        const float sa1 = sAp[row + 8] * alpha;
#pragma unroll
        for (int nt = 0; nt < 4; nt++) {
            const int col = n0 + c0 + nt * 8;
            const float sb0 = sBp[col];
            const float sb1 = sBp[col + 1];
            float f0 = (float)acc1[mt][nt][0] + (float)acc2[mt][nt][0] * (1.0f/256.0f);
            float f1 = (float)acc1[mt][nt][1] + (float)acc2[mt][nt][1] * (1.0f/256.0f);
            float f2 = (float)acc1[mt][nt][2] + (float)acc2[mt][nt][2] * (1.0f/256.0f);
            float f3 = (float)acc1[mt][nt][3] + (float)acc2[mt][nt][3] * (1.0f/256.0f);
            float* d0 = Cf + (size_t)z * strC + (size_t)row * N + col;
            float* d1 = Cf + (size_t)z * strC + (size_t)(row + 8) * N + col;
            d0[0] = f0 * sa0 * sb0;  d0[1] = f1 * sa0 * sb1;
            d1[0] = f2 * sa1 * sb0;  d1[1] = f3 * sa1 * sb1;
        }
    }
}

// ============================================================================
// bf16x3 GEMM for PV (kept from R3): C = alpha*A@B^T, K truncated at m0+128
// ============================================================================
template<int EPI, int MODE>
__global__ void __launch_bounds__(256, 1)
gemm_hmma(const bf16* __restrict__ Ahi, const bf16* __restrict__ Alo,
          const bf16* __restrict__ Bhi, const bf16* __restrict__ Blo,
          float* __restrict__ Cf,
          int M, int N, int K, size_t sA, size_t sB, size_t sC, float alpha)
{
    const int m0 = blockIdx.y * 128;
    const int n0 = blockIdx.x * 128;
    const int z  = blockIdx.z;
    int KT = K / 32;
    if (MODE == 2) { int kmax = m0 + 128; if (kmax < K) KT = kmax / 32; }

    extern __shared__ char smem[];
    const uint32_t sbase = smem_u32(smem);
    const int tid  = threadIdx.x;
    const int lane = tid & 31;
    const int wid  = tid >> 5;
    const int wm   = (wid >> 2) * 64;
    const int wn   = (wid & 3) * 32;

    const bf16* pAhi = Ahi + (size_t)z * sA;
    const bf16* pAlo = Alo + (size_t)z * sA;
    const bf16* pBhi = Bhi + (size_t)z * sB;
    const bf16* pBlo = Blo + (size_t)z * sB;

    const int lr = tid >> 2;
    const int sg = tid & 3;

    auto load_stage = [&](int s, int kt) {
        if (kt < KT) {
            const uint32_t st = sbase + (uint32_t)s * STAGE_BYTES;
            const size_t ko = (size_t)kt * 32 + sg * 8;
            const uint32_t so = (uint32_t)(lr * RSTRIDE + sg * 16);
            cp16(st + 0*ARR_BYTES + so,              pAhi + (size_t)(m0 + lr) * K + ko);
            cp16(st + 0*ARR_BYTES + so + 64*RSTRIDE, pAhi + (size_t)(m0 + lr + 64) * K + ko);
            cp16(st + 1*ARR_BYTES + so,              pAlo + (size_t)(m0 + lr) * K + ko);
            cp16(st + 1*ARR_BYTES + so + 64*RSTRIDE, pAlo + (size_t)(m0 + lr + 64) * K + ko);
            cp16(st + 2*ARR_BYTES + so,              pBhi + (size_t)(n0 + lr) * K + ko);
            cp16(st + 2*ARR_BYTES + so + 64*RSTRIDE, pBhi + (size_t)(n0 + lr + 64) * K + ko);
            cp16(st + 3*ARR_BYTES + so,              pBlo + (size_t)(n0 + lr) * K + ko);
            cp16(st + 3*ARR_BYTES + so + 64*RSTRIDE, pBlo + (size_t)(n0 + lr + 64) * K + ko);
        }
        asm volatile("cp.async.commit_group;" ::: "memory");
    };

    const int arow = lane & 15;
    const int akh  = lane >> 4;
    const int nrow = (lane & 7) + ((lane >> 4) << 3);
    const int bkh  = (lane >> 3) & 1;
    const uint32_t aoff = (uint32_t)((wm + arow) * RSTRIDE + akh * 16);
    const uint32_t boff = (uint32_t)((wn + nrow) * RSTRIDE + bkh * 16);

    float acc[4][4][4];
#pragma unroll
    for (int i = 0; i < 4; i++)
#pragma unroll
        for (int j = 0; j < 4; j++)
#pragma unroll
            for (int q = 0; q < 4; q++) acc[i][j][q] = 0.0f;

    load_stage(0, 0);
    load_stage(1, 1);
    load_stage(2, 2);

    for (int it = 0; it < KT; it++) {
        const int s = it & (NSTAGE - 1);
        asm volatile("cp.async.wait_group 2;" ::: "memory");
        __syncthreads();
        const uint32_t stg = sbase + (uint32_t)s * STAGE_BYTES;
#pragma unroll
        for (int ks = 0; ks < 2; ks++) {
            uint32_t ah[4][4], al[4][4];
#pragma unroll
            for (int mt = 0; mt < 4; mt++) {
                ldm4(ah[mt], stg + 0*ARR_BYTES + aoff + mt * (16 * RSTRIDE) + ks * 32);
                ldm4(al[mt], stg + 1*ARR_BYTES + aoff + mt * (16 * RSTRIDE) + ks * 32);
            }
#pragma unroll
            for (int ntp = 0; ntp < 2; ntp++) {
                uint32_t th[4], tl[4];
                ldm4(th, stg + 2*ARR_BYTES + boff + ntp * (16 * RSTRIDE) + ks * 32);
                ldm4(tl, stg + 3*ARR_BYTES + boff + ntp * (16 * RSTRIDE) + ks * 32);
#pragma unroll
                for (int mt = 0; mt < 4; mt++) {
#pragma unroll
                    for (int h = 0; h < 2; h++) {
                        const int nt = 2 * ntp + h;
                        uint32_t bh2[2] = {th[2*h], th[2*h+1]};
                        uint32_t bl2[2] = {tl[2*h], tl[2*h+1]};
                        mma_bf16(acc[mt][nt], ah[mt], bh2);
                        mma_bf16(acc[mt][nt], ah[mt], bl2);
                        mma_bf16(acc[mt][nt], al[mt], bh2);
                    }
                }
            }
        }
        load_stage((it + 3) & (NSTAGE - 1), it + 3);
    }

    const int r0 = wm + (lane >> 2);
    const int c0 = wn + (lane & 3) * 2;
#pragma unroll
    for (int mt = 0; mt < 4; mt++) {
#pragma unroll
        for (int nt = 0; nt < 4; nt++) {
            const int row = m0 + r0 + mt * 16;
            const int col = n0 + c0 + nt * 8;
            float* d0 = Cf + (size_t)z * sC + (size_t)row * N + col;
            float* d1 = Cf + (size_t)z * sC + (size_t)(row + 8) * N + col;
            d0[0] = acc[mt][nt][0] * alpha;  d0[1] = acc[mt][nt][1] * alpha;
            d1[0] = acc[mt][nt][2] * alpha;  d1[1] = acc[mt][nt][3] * alpha;
        }
    }
}

// ============================================================================
// quantization / transpose / softmax
// ============================================================================
// per-row two-level int8 quantization; row length = DD
__global__ __launch_bounds__(256) void rowquant_kernel(
    const float* __restrict__ in, int8_t* __restrict__ q1, int8_t* __restrict__ q2,
    float* __restrict__ s)
{
    const size_t base = (size_t)blockIdx.x * DD;
    const int tid = threadIdx.x;
    float v[8];
    float m = 0.0f;
#pragma unroll
    for (int j = 0; j < 8; j++) {
        v[j] = in[base + tid + j * 256];
        m = fmaxf(m, fabsf(v[j]));
    }
    __shared__ float red[256];
    red[tid] = m; __syncthreads();
    for (int st = 128; st > 0; st >>= 1) {
        if (tid < st) red[tid] = fmaxf(red[tid], red[tid + st]);
        __syncthreads();
    }
    const float mx = red[0];
    const float sc  = (mx > 0.0f) ? mx / 127.0f : 1.0f;
    const float inv = (mx > 0.0f) ? 127.0f / mx : 0.0f;
    const float inv2 = 256.0f / sc;
    if (tid == 0) s[blockIdx.x] = sc;
#pragma unroll
    for (int j = 0; j < 8; j++) {
        const int i = tid + j * 256;
        int a = clamp127(__float2int_rn(v[j] * inv));
        float r = v[j] - (float)a * sc;
        int b = clamp127(__float2int_rn(r * inv2));
        q1[base + i] = (int8_t)a;
        q2[base + i] = (int8_t)b;
    }
}

// column |max| partials of W (DD x DD): grid (DD/256, 16)
__global__ void colmax1_kernel(const float* __restrict__ W, float* __restrict__ part)
{
    const int c = blockIdx.x * 256 + threadIdx.x;
    const int r0 = blockIdx.y * (DD / 16);
    float m = 0.0f;
    for (int r = r0; r < r0 + DD / 16; r++)
        m = fmaxf(m, fabsf(W[(size_t)r * DD + c]));
    part[(size_t)blockIdx.y * DD + c] = m;
}
__global__ void colmax2_kernel(const float* __restrict__ part, float* __restrict__ s)
{
    const int c = blockIdx.x * 256 + threadIdx.x;
    float m = 0.0f;
#pragma unroll
    for (int j = 0; j < 16; j++) m = fmaxf(m, part[(size_t)j * DD + c]);
    s[c] = (m > 0.0f) ? m / 127.0f : 1.0f;
}

// transpose W and quantize with per-column scale s (already max/127)
__global__ void transpose_quant_kernel(const float* __restrict__ W,
                                       const float* __restrict__ s,
                                       int8_t* __restrict__ q1, int8_t* __restrict__ q2)
{
    __shared__ float t[32][33];
    const int c0 = blockIdx.x * 32, r0 = blockIdx.y * 32;
    const int tx = threadIdx.x, ty = threadIdx.y;
#pragma unroll
    for (int j = 0; j < 32; j += 8)
        t[ty + j][tx] = W[(size_t)(r0 + ty + j) * DD + c0 + tx];
    __syncthreads();
#pragma unroll
    for (int j = 0; j < 32; j += 8) {
        const int col = c0 + ty + j;
        const int row = r0 + tx;
        const float sc = s[col];
        const float v = t[tx][ty + j];
        int a = clamp127(__float2int_rn(v / sc));
        float r = v - (float)a * sc;
        int b = clamp127(__float2int_rn(r * 256.0f / sc));
        const size_t o = (size_t)col * DD + row;
        q1[o] = (int8_t)a;
        q2[o] = (int8_t)b;
    }
}

// V fp32 [B,S,D] -> bf16 hi/lo [B,D,S]
__global__ void vsplit_t_kernel(const float* __restrict__ V,
                                bf16* __restrict__ hi, bf16* __restrict__ lo)
{
    __shared__ float t[32][33];
    const int b = blockIdx.z;
    const int d0 = blockIdx.x * 32, s0 = blockIdx.y * 32;
    const int tx = threadIdx.x, ty = threadIdx.y;
    const float* src = V + (size_t)b * SS * DD;
#pragma unroll
    for (int j = 0; j < 32; j += 8)
        t[ty + j][tx] = src[(size_t)(s0 + ty + j) * DD + d0 + tx];
    __syncthreads();
#pragma unroll
    for (int j = 0; j < 32; j += 8) {
        const float v = t[tx][ty + j];
        bf16 h = __float2bfloat16(v);
        const size_t o = (size_t)b * DD * SS + (size_t)(d0 + ty + j) * SS + s0 + tx;
        hi[o] = h;
        lo[o] = __float2bfloat16(v - __bfloat162float(h));
    }
}

// causal softmax over fp32 P rows -> split bf16
__global__ __launch_bounds__(256) void softmax_split_kernel(
    const float* __restrict__ P, bf16* __restrict__ Phi, bf16* __restrict__ Plo)
{
    const int row = blockIdx.x & (SS - 1);
    const int b   = blockIdx.x >> 11;
    const size_t base = ((size_t)b * SS + row) * SS;
    const int L = row + 1;
    const int tid = threadIdx.x;

    float v[8];
    float m = -INFINITY;
#pragma unroll
    for (int j = 0; j < 8; j++) {
        int i = tid + j * 256;
        v[j] = (i < L) ? P[base + i] : -INFINITY;
        m = fmaxf(m, v[j]);
    }
    __shared__ float red[256];
    red[tid] = m; __syncthreads();
    for (int s2 = 128; s2 > 0; s2 >>= 1) {
        if (tid < s2) red[tid] = fmaxf(red[tid], red[tid + s2]);
        __syncthreads();
    }
    m = red[0]; __syncthreads();

    float sum = 0.0f;
#pragma unroll
    for (int j = 0; j < 8; j++) {
        int i = tid + j * 256;
        if (i < L) { v[j] = __expf(v[j] - m); sum += v[j]; }
    }
    red[tid] = sum; __syncthreads();
    for (int s2 = 128; s2 > 0; s2 >>= 1) {
        if (tid < s2) red[tid] += red[tid + s2];
        __syncthreads();
    }
    const float inv = 1.0f / red[0];
    __syncthreads();

#pragma unroll
    for (int j = 0; j < 8; j++) {
        int i = tid + j * 256;
        if (i < L) {
            float val = v[j] * inv;
            bf16 h = __float2bfloat16(val);
            Phi[base + i] = h;
            Plo[base + i] = __float2bfloat16(val - __bfloat162float(h));
        }
    }
    const bf16 z16 = __float2bfloat16(0.0f);
    for (int i = L + tid; i < SS; i += 256) { Phi[base + i] = z16; Plo[base + i] = z16; }
}

// ---------------- launch ----------------
extern "C" void kernel_launch(void* const* d_in, const int* in_sizes, int n_in,
                              void* d_out, int out_size)
{
    const float* x  = (const float*)d_in[0];
    const float* W[3] = { (const float*)d_in[1], (const float*)d_in[2], (const float*)d_in[3] };
    float* out = (float*)d_out;

    int8_t *x1, *x2, *W1T, *W2T, *Q1, *Q2, *K1, *K2;
    float *sx, *sW, *cpart, *QKV, *sQ, *sK, *P;
    bf16 *Vthi, *Vtlo, *Phi, *Plo;
    cudaGetSymbolAddress((void**)&x1,   g_x1);
    cudaGetSymbolAddress((void**)&x2,   g_x2);
    cudaGetSymbolAddress((void**)&sx,   g_sx);
    cudaGetSymbolAddress((void**)&W1T,  g_W1T);
    cudaGetSymbolAddress((void**)&W2T,  g_W2T);
    cudaGetSymbolAddress((void**)&sW,   g_sW);
    cudaGetSymbolAddress((void**)&cpart,g_cpart);
    cudaGetSymbolAddress((void**)&QKV,  g_QKV);
    cudaGetSymbolAddress((void**)&Q1,   g_Q1);
    cudaGetSymbolAddress((void**)&Q2,   g_Q2);
    cudaGetSymbolAddress((void**)&K1,   g_K1);
    cudaGetSymbolAddress((void**)&K2,   g_K2);
    cudaGetSymbolAddress((void**)&sQ,   g_sQ);
    cudaGetSymbolAddress((void**)&sK,   g_sK);
    cudaGetSymbolAddress((void**)&Vthi, g_Vthi);
    cudaGetSymbolAddress((void**)&Vtlo, g_Vtlo);
    cudaGetSymbolAddress((void**)&P,    g_P);
    cudaGetSymbolAddress((void**)&Phi,  g_Phi);
    cudaGetSymbolAddress((void**)&Plo,  g_Plo);

    cudaFuncSetAttribute(gemm_s8<0>,     cudaFuncAttributeMaxDynamicSharedMemorySize, SMEM_GEMM);
    cudaFuncSetAttribute(gemm_s8<1>,     cudaFuncAttributeMaxDynamicSharedMemorySize, SMEM_GEMM);
    cudaFuncSetAttribute(gemm_hmma<0,2>, cudaFuncAttributeMaxDynamicSharedMemorySize, SMEM_GEMM);

    const size_t WSZ = (size_t)DD * DD;
    const size_t QSZ = (size_t)BB * SS * DD;
    const dim3 t32(32, 8);

    // quantize x (per row over D)
    rowquant_kernel<<<XROWS, 256>>>(x, x1, x2, sx);

    // per-column scales of W, then transpose+quantize -> W^T int8x2
    for (int w = 0; w < 3; w++) {
        colmax1_kernel<<<dim3(DD/256, 16), 256>>>(W[w], cpart);
        colmax2_kernel<<<DD/256, 256>>>(cpart, sW + w*DD);
        transpose_quant_kernel<<<dim3(DD/32, DD/32), t32>>>(W[w], sW + w*DD,
                                                            W1T + w*WSZ, W2T + w*WSZ);
    }

    // QKV projections (fused z=3) -> fp32 Q,K,V
    dim3 g1(DD/128, XROWS/128, 3);
    gemm_s8<0><<<g1, 256, SMEM_GEMM>>>(x1, x2, W1T, W2T, sx, sW, QKV,
                                       XROWS, DD, DD, 0, WSZ, QSZ, 0, DD, 1.0f);

    // requantize Q, K per row; split+transpose V
    rowquant_kernel<<<XROWS, 256>>>(QKV,           Q1, Q2, sQ);
    rowquant_kernel<<<XROWS, 256>>>(QKV + QSZ,     K1, K2, sK);
    vsplit_t_kernel<<<dim3(DD/32, SS/32, BB), t32>>>(QKV + 2*QSZ, Vthi, Vtlo);

    // scores: P[b] = scale * Q[b] @ K[b]^T (skip fully-masked tiles)
    dim3 g2(SS/128, SS/128, BB);
    const float scale = 1.0f / sqrtf((float)DD);
    gemm_s8<1><<<g2, 256, SMEM_GEMM>>>(Q1, Q2, K1, K2, sQ, sK, P,
                                       SS, SS, DD, (size_t)SS*DD, (size_t)SS*DD,
                                       (size_t)SS*SS, SS, SS, scale);

    // causal softmax -> split bf16 P
    softmax_split_kernel<<<BB * SS, 256>>>(P, Phi, Plo);

    // out[b] = P[b] @ V[b] (bf16x3, K truncated at diagonal)
    dim3 g3(DD/128, SS/128, BB);
    gemm_hmma<0,2><<<g3, 256, SMEM_GEMM>>>(Phi, Plo, Vthi, Vtlo, out,
                                           SS, DD, SS, (size_t)SS*SS, (size_t)SS*DD,
                                           (size_t)SS*DD, 1.0f);
}

// round 5
// speedup vs baseline: 1.6295x; 1.6295x over previous
#include <cuda_runtime.h>
#include <cuda_bf16.h>
#include <cstdint>
#include <math.h>

#define BB 4
#define SS 2048
#define DD 2048
typedef __nv_bfloat16 bf16;

// ---------------- scratch (static device globals; no allocs) ----------------
__device__ bf16 g_xhi[(size_t)BB*SS*DD], g_xlo[(size_t)BB*SS*DD];
__device__ bf16 g_Wthi[3][(size_t)DD*DD], g_Wtlo[3][(size_t)DD*DD];
__device__ bf16 g_QKVhi[3][(size_t)BB*SS*DD], g_QKVlo[3][(size_t)BB*SS*DD];
__device__ bf16 g_Vthi[(size_t)BB*SS*DD], g_Vtlo[(size_t)BB*SS*DD];
__device__ float g_P[(size_t)BB*SS*SS];
__device__ bf16 g_Phi[(size_t)BB*SS*SS], g_Plo[(size_t)BB*SS*SS];

// ---------------- helpers ----------------
__device__ __forceinline__ uint32_t smem_u32(const void* p) {
    uint32_t a;
    asm("{ .reg .u64 t; cvta.to.shared.u64 t, %1; cvt.u32.u64 %0, t; }" : "=r"(a) : "l"(p));
    return a;
}
__device__ __forceinline__ void cp16(uint32_t dst, const void* src) {
    asm volatile("cp.async.cg.shared.global [%0], [%1], 16;" :: "r"(dst), "l"(src));
}
__device__ __forceinline__ void ldm4(uint32_t* r, uint32_t addr) {
    asm volatile("ldmatrix.sync.aligned.m8n8.x4.shared.b16 {%0,%1,%2,%3}, [%4];"
                 : "=r"(r[0]), "=r"(r[1]), "=r"(r[2]), "=r"(r[3]) : "r"(addr));
}
__device__ __forceinline__ void mma_bf16(float c[4], const uint32_t a[4],
                                         uint32_t b0, uint32_t b1) {
    asm volatile(
        "mma.sync.aligned.m16n8k16.row.col.f32.bf16.bf16.f32 "
        "{%0,%1,%2,%3}, {%4,%5,%6,%7}, {%8,%9}, {%0,%1,%2,%3};"
        : "+f"(c[0]), "+f"(c[1]), "+f"(c[2]), "+f"(c[3])
        : "r"(a[0]), "r"(a[1]), "r"(a[2]), "r"(a[3]), "r"(b0), "r"(b1));
}
__device__ __forceinline__ uint32_t pack2(bf16 a, bf16 b) {
    return (uint32_t)__bfloat16_as_ushort(a) | ((uint32_t)__bfloat16_as_ushort(b) << 16);
}

// ---------------- GEMM geometry: CTA 128x256, warp 64x64, BK=32, 3 stages ----
#define RST 80                       // 64B data + 16B pad per row
#define A_BYTES (128 * RST)          // 10240
#define B_BYTES (256 * RST)          // 20480
#define OAHI 0
#define OALO A_BYTES
#define OBHI (2 * A_BYTES)
#define OBLO (2 * A_BYTES + B_BYTES)
#define STG_BYTES (2 * A_BYTES + 2 * B_BYTES)   // 61440
#define NST 3
#define SMEM_G (NST * STG_BYTES)     // 184320

// C[z] = alpha * A[z] @ B[z]^T with bf16 hi/lo x3.
// A: [M,K] rows; B: [N,K] rows (K-major). EPI 0: fp32 out. EPI 1: split bf16 out.
// MODE 0: dense. MODE 1: skip tiles fully above causal diagonal. MODE 2: K trunc at m0+128.
template<int EPI, int MODE>
__global__ void __launch_bounds__(256, 1)
gemm_hmma(const bf16* __restrict__ Ahi, const bf16* __restrict__ Alo,
          const bf16* __restrict__ Bhi, const bf16* __restrict__ Blo,
          float* __restrict__ Cf, bf16* __restrict__ Chi, bf16* __restrict__ Clo,
          int M, int N, int K, size_t sA, size_t sB, size_t sC, float alpha)
{
    const int m0 = blockIdx.y * 128;
    const int n0 = blockIdx.x * 256;
    const int z  = blockIdx.z;
    if (MODE == 1 && n0 > m0) return;              // fully-masked score tile
    int KT = K / 32;
    if (MODE == 2) { int kmax = m0 + 128; if (kmax < K) KT = kmax / 32; }

    extern __shared__ char smem[];
    const uint32_t sbase = smem_u32(smem);
    const int tid  = threadIdx.x;
    const int lane = tid & 31;
    const int wid  = tid >> 5;
    const int wm   = (wid >> 2) * 64;              // 0 / 64
    const int wn   = (wid & 3) * 64;               // 0..192

    const bf16* pAhi = Ahi + (size_t)z * sA;
    const bf16* pAlo = Alo + (size_t)z * sA;
    const bf16* pBhi = Bhi + (size_t)z * sB;
    const bf16* pBlo = Blo + (size_t)z * sB;

    const int lr = tid >> 2;       // 0..63
    const int sg = tid & 3;        // 16B segment

    auto load_stage = [&](int s, int kt) {
        if (kt < KT) {
            const uint32_t st = sbase + (uint32_t)s * STG_BYTES;
            const size_t ko = (size_t)kt * 32 + sg * 8;
            const uint32_t so = (uint32_t)(lr * RST + sg * 16);
#pragma unroll
            for (int h = 0; h < 2; h++) {          // A: 128 rows
                const int r = lr + h * 64;
                cp16(st + OAHI + so + h * (64 * RST), pAhi + (size_t)(m0 + r) * K + ko);
                cp16(st + OALO + so + h * (64 * RST), pAlo + (size_t)(m0 + r) * K + ko);
            }
#pragma unroll
            for (int h = 0; h < 4; h++) {          // B: 256 rows
                const int r = lr + h * 64;
                cp16(st + OBHI + so + h * (64 * RST), pBhi + (size_t)(n0 + r) * K + ko);
                cp16(st + OBLO + so + h * (64 * RST), pBlo + (size_t)(n0 + r) * K + ko);
            }
        }
        asm volatile("cp.async.commit_group;" ::: "memory");
    };

    // ldmatrix per-lane address components
    const int arow = lane & 15;
    const int akh  = lane >> 4;
    const int nrow = (lane & 7) + ((lane >> 4) << 3);
    const int bkh  = (lane >> 3) & 1;
    const uint32_t aoff = (uint32_t)((wm + arow) * RST + akh * 16);
    const uint32_t boff = (uint32_t)((wn + nrow) * RST + bkh * 16);

    float acc[4][8][4];
#pragma unroll
    for (int i = 0; i < 4; i++)
#pragma unroll
        for (int j = 0; j < 8; j++)
#pragma unroll
            for (int q = 0; q < 4; q++) acc[i][j][q] = 0.0f;

    load_stage(0, 0);
    load_stage(1, 1);

    for (int it = 0; it < KT; it++) {
        const int s  = it % NST;
        asm volatile("cp.async.wait_group 1;" ::: "memory");
        __syncthreads();
        const uint32_t stg = sbase + (uint32_t)s * STG_BYTES;
#pragma unroll
        for (int ks = 0; ks < 2; ks++) {
            uint32_t bh[16], bl[16];
#pragma unroll
            for (int p = 0; p < 4; p++) {
                ldm4(bh + 4 * p, stg + OBHI + boff + p * (16 * RST) + ks * 32);
                ldm4(bl + 4 * p, stg + OBLO + boff + p * (16 * RST) + ks * 32);
            }
#pragma unroll
            for (int mt = 0; mt < 4; mt++) {
                uint32_t ah[4], al[4];
                ldm4(ah, stg + OAHI + aoff + mt * (16 * RST) + ks * 32);
                ldm4(al, stg + OALO + aoff + mt * (16 * RST) + ks * 32);
#pragma unroll
                for (int nt = 0; nt < 8; nt++) {
                    const uint32_t b0h = bh[(nt >> 1) * 4 + (nt & 1) * 2];
                    const uint32_t b1h = bh[(nt >> 1) * 4 + (nt & 1) * 2 + 1];
                    const uint32_t b0l = bl[(nt >> 1) * 4 + (nt & 1) * 2];
                    const uint32_t b1l = bl[(nt >> 1) * 4 + (nt & 1) * 2 + 1];
                    mma_bf16(acc[mt][nt], ah, b0h, b1h);
                    mma_bf16(acc[mt][nt], ah, b0l, b1l);
                    mma_bf16(acc[mt][nt], al, b0h, b1h);
                }
            }
        }
        load_stage((it + 2) % NST, it + 2);
    }

    // ---- epilogue ----
    const int r0 = wm + (lane >> 2);
    const int c0 = wn + (lane & 3) * 2;
#pragma unroll
    for (int mt = 0; mt < 4; mt++) {
#pragma unroll
        for (int nt = 0; nt < 8; nt++) {
            const int row = m0 + r0 + mt * 16;
            const int col = n0 + c0 + nt * 8;
            const float v0 = acc[mt][nt][0] * alpha, v1 = acc[mt][nt][1] * alpha;
            const float v2 = acc[mt][nt][2] * alpha, v3 = acc[mt][nt][3] * alpha;
            if (EPI == 0) {
                float* d0 = Cf + (size_t)z * sC + (size_t)row * N + col;
                float* d1 = Cf + (size_t)z * sC + (size_t)(row + 8) * N + col;
                d0[0] = v0; d0[1] = v1;
                d1[0] = v2; d1[1] = v3;
            } else {
                bf16 h0 = __float2bfloat16(v0), h1 = __float2bfloat16(v1);
                bf16 h2 = __float2bfloat16(v2), h3 = __float2bfloat16(v3);
                bf16 l0 = __float2bfloat16(v0 - __bfloat162float(h0));
                bf16 l1 = __float2bfloat16(v1 - __bfloat162float(h1));
                bf16 l2 = __float2bfloat16(v2 - __bfloat162float(h2));
                bf16 l3 = __float2bfloat16(v3 - __bfloat162float(h3));
                const size_t o0 = (size_t)z * sC + (size_t)row * N + col;
                const size_t o1 = (size_t)z * sC + (size_t)(row + 8) * N + col;
                *reinterpret_cast<uint32_t*>(Chi + o0) = pack2(h0, h1);
                *reinterpret_cast<uint32_t*>(Chi + o1) = pack2(h2, h3);
                *reinterpret_cast<uint32_t*>(Clo + o0) = pack2(l0, l1);
                *reinterpret_cast<uint32_t*>(Clo + o1) = pack2(l2, l3);
            }
        }
    }
}

// ---------------- conversion / transpose / softmax ----------------
__global__ __launch_bounds__(256) void split_kernel(
    const float* __restrict__ in, bf16* __restrict__ hi, bf16* __restrict__ lo, size_t n)
{
    for (size_t i = (size_t)blockIdx.x * 256 + threadIdx.x; i < n; i += (size_t)gridDim.x * 256) {
        float v = in[i];
        bf16 h = __float2bfloat16(v);
        hi[i] = h;
        lo[i] = __float2bfloat16(v - __bfloat162float(h));
    }
}

__global__ void transpose_split_kernel(const float* __restrict__ in,
                                       bf16* __restrict__ hi, bf16* __restrict__ lo)
{
    __shared__ float t[32][33];
    const int c0 = blockIdx.x * 32, rr0 = blockIdx.y * 32;
    const int tx = threadIdx.x, ty = threadIdx.y;
#pragma unroll
    for (int j = 0; j < 32; j += 8)
        t[ty + j][tx] = in[(size_t)(rr0 + ty + j) * DD + c0 + tx];
    __syncthreads();
#pragma unroll
    for (int j = 0; j < 32; j += 8) {
        float v = t[tx][ty + j];
        bf16 h = __float2bfloat16(v);
        size_t o = (size_t)(c0 + ty + j) * DD + rr0 + tx;
        hi[o] = h;
        lo[o] = __float2bfloat16(v - __bfloat162float(h));
    }
}

// bf16 [B,S,D] -> [B,D,S]; grid.z = BB*2 selects batch and hi/lo pair
__global__ void transpose_pair_kernel(const bf16* __restrict__ src_hi,
                                      const bf16* __restrict__ src_lo,
                                      bf16* __restrict__ dst_hi,
                                      bf16* __restrict__ dst_lo)
{
    __shared__ bf16 t[32][33];
    const int b = blockIdx.z >> 1;
    const bf16* src = (blockIdx.z & 1) ? src_lo : src_hi;
    bf16* dst = (blockIdx.z & 1) ? dst_lo : dst_hi;
    const int d0 = blockIdx.x * 32, s0 = blockIdx.y * 32;
    const int tx = threadIdx.x, ty = threadIdx.y;
    const bf16* s = src + (size_t)b * SS * DD;
    bf16* d = dst + (size_t)b * DD * SS;
#pragma unroll
    for (int j = 0; j < 32; j += 8)
        t[ty + j][tx] = s[(size_t)(s0 + ty + j) * DD + d0 + tx];
    __syncthreads();
#pragma unroll
    for (int j = 0; j < 32; j += 8)
        d[(size_t)(d0 + ty + j) * SS + s0 + tx] = t[tx][ty + j];
}

__global__ __launch_bounds__(256) void softmax_split_kernel(
    const float* __restrict__ P, bf16* __restrict__ Phi, bf16* __restrict__ Plo)
{
    const int row = blockIdx.x & (SS - 1);
    const int b   = blockIdx.x >> 11;
    const size_t base = ((size_t)b * SS + row) * SS;
    const int L = row + 1;
    const int tid = threadIdx.x;

    float v[8];
    float m = -INFINITY;
#pragma unroll
    for (int j = 0; j < 8; j++) {
        int i = tid + j * 256;
        v[j] = (i < L) ? P[base + i] : -INFINITY;
        m = fmaxf(m, v[j]);
    }
    __shared__ float red[256];
    red[tid] = m; __syncthreads();
    for (int s2 = 128; s2 > 0; s2 >>= 1) {
        if (tid < s2) red[tid] = fmaxf(red[tid], red[tid + s2]);
        __syncthreads();
    }
    m = red[0]; __syncthreads();

    float sum = 0.0f;
#pragma unroll
    for (int j = 0; j < 8; j++) {
        int i = tid + j * 256;
        if (i < L) { v[j] = __expf(v[j] - m); sum += v[j]; }
    }
    red[tid] = sum; __syncthreads();
    for (int s2 = 128; s2 > 0; s2 >>= 1) {
        if (tid < s2) red[tid] += red[tid + s2];
        __syncthreads();
    }
    const float inv = 1.0f / red[0];
    __syncthreads();

#pragma unroll
    for (int j = 0; j < 8; j++) {
        int i = tid + j * 256;
        if (i < L) {
            float val = v[j] * inv;
            bf16 h = __float2bfloat16(val);
            Phi[base + i] = h;
            Plo[base + i] = __float2bfloat16(val - __bfloat162float(h));
        }
    }
    const bf16 z16 = __float2bfloat16(0.0f);
    for (int i = L + tid; i < SS; i += 256) { Phi[base + i] = z16; Plo[base + i] = z16; }
}

// ---------------- launch ----------------
extern "C" void kernel_launch(void* const* d_in, const int* in_sizes, int n_in,
                              void* d_out, int out_size)
{
    const float* x  = (const float*)d_in[0];
    const float* Wq = (const float*)d_in[1];
    const float* Wk = (const float*)d_in[2];
    const float* Wv = (const float*)d_in[3];
    float* out = (float*)d_out;

    bf16 *xhi, *xlo, *Wthi, *Wtlo, *QKVhi, *QKVlo, *Vthi, *Vtlo, *Phi, *Plo;
    float* P;
    cudaGetSymbolAddress((void**)&xhi,   g_xhi);
    cudaGetSymbolAddress((void**)&xlo,   g_xlo);
    cudaGetSymbolAddress((void**)&Wthi,  g_Wthi);
    cudaGetSymbolAddress((void**)&Wtlo,  g_Wtlo);
    cudaGetSymbolAddress((void**)&QKVhi, g_QKVhi);
    cudaGetSymbolAddress((void**)&QKVlo, g_QKVlo);
    cudaGetSymbolAddress((void**)&Vthi,  g_Vthi);
    cudaGetSymbolAddress((void**)&Vtlo,  g_Vtlo);
    cudaGetSymbolAddress((void**)&P,     g_P);
    cudaGetSymbolAddress((void**)&Phi,   g_Phi);
    cudaGetSymbolAddress((void**)&Plo,   g_Plo);

    cudaFuncSetAttribute(gemm_hmma<1,0>, cudaFuncAttributeMaxDynamicSharedMemorySize, SMEM_G);
    cudaFuncSetAttribute(gemm_hmma<0,1>, cudaFuncAttributeMaxDynamicSharedMemorySize, SMEM_G);
    cudaFuncSetAttribute(gemm_hmma<0,2>, cudaFuncAttributeMaxDynamicSharedMemorySize, SMEM_G);

    const size_t WSZ = (size_t)DD * DD;
    const size_t QSZ = (size_t)BB * SS * DD;
    const dim3 t32(32, 8);

    // convert inputs
    split_kernel<<<8192, 256>>>(x, xhi, xlo, QSZ);
    transpose_split_kernel<<<dim3(DD/32, DD/32), t32>>>(Wq, Wthi + 0*WSZ, Wtlo + 0*WSZ);
    transpose_split_kernel<<<dim3(DD/32, DD/32), t32>>>(Wk, Wthi + 1*WSZ, Wtlo + 1*WSZ);
    transpose_split_kernel<<<dim3(DD/32, DD/32), t32>>>(Wv, Wthi + 2*WSZ, Wtlo + 2*WSZ);

    // QKV projections in one launch: z selects W slice and output slice
    dim3 g1(DD/256, (BB*SS)/128, 3);
    gemm_hmma<1,0><<<g1, 256, SMEM_G>>>(xhi, xlo, Wthi, Wtlo,
                                        nullptr, QKVhi, QKVlo,
                                        BB*SS, DD, DD, 0, WSZ, QSZ, 1.0f);

    // V^T (hi+lo fused in one launch)
    transpose_pair_kernel<<<dim3(DD/32, SS/32, BB*2), t32>>>(QKVhi + 2*QSZ, QKVlo + 2*QSZ,
                                                             Vthi, Vtlo);

    // scores: P[b] = scale * Q[b] @ K[b]^T (skip fully-masked tiles)
    dim3 g2(SS/256, SS/128, BB);
    const float scale = 1.0f / sqrtf((float)DD);
    gemm_hmma<0,1><<<g2, 256, SMEM_G>>>(QKVhi, QKVlo, QKVhi + QSZ, QKVlo + QSZ,
                                        P, nullptr, nullptr,
                                        SS, SS, DD, (size_t)SS*DD, (size_t)SS*DD,
                                        (size_t)SS*SS, scale);

    // causal softmax -> split bf16 P
    softmax_split_kernel<<<BB * SS, 256>>>(P, Phi, Plo);

    // out[b] = P[b] @ V[b] (K truncated at diagonal)
    dim3 g3(DD/256, SS/128, BB);
    gemm_hmma<0,2><<<g3, 256, SMEM_G>>>(Phi, Plo, Vthi, Vtlo,
                                        out, nullptr, nullptr,
                                        SS, DD, SS, (size_t)SS*SS, (size_t)SS*DD,
                                        (size_t)SS*DD, 1.0f);
}

// round 6
// speedup vs baseline: 3.6605x; 2.2463x over previous
#include <cuda_runtime.h>
#include <cuda_fp16.h>
#include <cstdint>
#include <math.h>

#define BB 4
#define SS 2048
#define DD 2048
typedef __half h16;

// ---------------- scratch (static device globals; no allocs) ----------------
__device__ h16  g_xhi[(size_t)BB*SS*DD], g_xlo[(size_t)BB*SS*DD];
__device__ h16  g_Wt[3][(size_t)DD*DD];
__device__ h16  g_Qhi[(size_t)BB*SS*DD], g_Qlo[(size_t)BB*SS*DD];
__device__ h16  g_KV[2][(size_t)BB*SS*DD];        // K single, V single
__device__ h16  g_VT[(size_t)BB*SS*DD];           // V^T [B,D,S]
__device__ float g_P[(size_t)BB*SS*SS];
__device__ h16  g_Phi[(size_t)BB*SS*SS], g_Plo[(size_t)BB*SS*SS];

// ---------------- helpers ----------------
__device__ __forceinline__ uint32_t smem_u32(const void* p) {
    uint32_t a;
    asm("{ .reg .u64 t; cvta.to.shared.u64 t, %1; cvt.u32.u64 %0, t; }" : "=r"(a) : "l"(p));
    return a;
}
__device__ __forceinline__ void cp16(uint32_t dst, const void* src) {
    asm volatile("cp.async.cg.shared.global [%0], [%1], 16;" :: "r"(dst), "l"(src));
}
__device__ __forceinline__ void ldm4(uint32_t* r, uint32_t addr) {
    asm volatile("ldmatrix.sync.aligned.m8n8.x4.shared.b16 {%0,%1,%2,%3}, [%4];"
                 : "=r"(r[0]), "=r"(r[1]), "=r"(r[2]), "=r"(r[3]) : "r"(addr));
}
__device__ __forceinline__ void mma_f16(float c[4], const uint32_t a[4],
                                        uint32_t b0, uint32_t b1) {
    asm volatile(
        "mma.sync.aligned.m16n8k16.row.col.f32.f16.f16.f32 "
        "{%0,%1,%2,%3}, {%4,%5,%6,%7}, {%8,%9}, {%0,%1,%2,%3};"
        : "+f"(c[0]), "+f"(c[1]), "+f"(c[2]), "+f"(c[3])
        : "r"(a[0]), "r"(a[1]), "r"(a[2]), "r"(a[3]), "r"(b0), "r"(b1));
}
__device__ __forceinline__ uint32_t pack2(h16 a, h16 b) {
    return (uint32_t)__half_as_ushort(a) | ((uint32_t)__half_as_ushort(b) << 16);
}

// ---------------- GEMM geometry: CTA 128x128, warp 64x32, BK=64, 4 stages ----
#define RST 144                      // 128B data + 16B pad
#define ARR_B (128 * RST)            // 18432
#define OAHI 0
#define OALO ARR_B
#define OBS  (2 * ARR_B)
#define STG_B (3 * ARR_B)            // 55296
#define NST 4
#define SMEM_G (NST * STG_B)         // 221184

// C[z] = alpha * (Ahi+Alo)[z] @ Bs[z]^T      (fp16 asymmetric 2-MMA)
// A: [M,K] rows fp16 hi/lo; Bs: [N,K] rows fp16 single.
// EPI 0: fp32 to Cf.
// EPI 1 (QKV): z==0 -> split fp16 to Chi/Clo; z>=1 -> single fp16 to Cs+(z-1)*strCs.
// MODE 0: dense. MODE 1: skip tiles fully above causal diag. MODE 2: K trunc at m0+128.
template<int EPI, int MODE>
__global__ void __launch_bounds__(256, 1)
gemm_f16(const h16* __restrict__ Ahi, const h16* __restrict__ Alo,
         const h16* __restrict__ Bs,
         float* __restrict__ Cf, h16* __restrict__ Chi, h16* __restrict__ Clo,
         h16* __restrict__ Cs,
         int M, int N, int K, size_t sA, size_t sB, size_t sC, size_t strCs,
         float alpha)
{
    const int m0 = blockIdx.y * 128;
    const int n0 = blockIdx.x * 128;
    const int z  = blockIdx.z;
    if (MODE == 1 && n0 > m0) return;
    int KT = K / 64;
    if (MODE == 2) { int kmax = m0 + 128; if (kmax < K) KT = kmax / 64; }

    extern __shared__ char smem[];
    const uint32_t sbase = smem_u32(smem);
    const int tid  = threadIdx.x;
    const int lane = tid & 31;
    const int wid  = tid >> 5;
    const int wm   = (wid >> 2) * 64;
    const int wn   = (wid & 3) * 32;

    const h16* pAhi = Ahi + (size_t)z * sA;
    const h16* pAlo = Alo + (size_t)z * sA;
    const h16* pBs  = Bs  + (size_t)z * sB;

    auto load_stage = [&](int s, int kt) {
        if (kt < KT) {
            const uint32_t st = sbase + (uint32_t)s * STG_B;
            const size_t ko = (size_t)kt * 64;
#pragma unroll
            for (int i = 0; i < 4; i++) {
                const int slot = tid + i * 256;       // 0..1023
                const int row = slot >> 3;
                const int seg = slot & 7;
                const uint32_t so = (uint32_t)(row * RST + seg * 16);
                const size_t go = ko + seg * 8;
                cp16(st + OAHI + so, pAhi + (size_t)(m0 + row) * K + go);
                cp16(st + OALO + so, pAlo + (size_t)(m0 + row) * K + go);
                cp16(st + OBS  + so, pBs  + (size_t)(n0 + row) * K + go);
            }
        }
        asm volatile("cp.async.commit_group;" ::: "memory");
    };

    // ldmatrix per-lane address components
    const int arow = lane & 15;
    const int akh  = lane >> 4;
    const int nrow = (lane & 7) + ((lane >> 4) << 3);
    const int bkh  = (lane >> 3) & 1;
    const uint32_t aoff = (uint32_t)((wm + arow) * RST + akh * 16);
    const uint32_t boff = (uint32_t)((wn + nrow) * RST + bkh * 16);

    float acc[4][4][4];
#pragma unroll
    for (int i = 0; i < 4; i++)
#pragma unroll
        for (int j = 0; j < 4; j++)
#pragma unroll
            for (int q = 0; q < 4; q++) acc[i][j][q] = 0.0f;

    load_stage(0, 0);
    load_stage(1, 1);
    load_stage(2, 2);

    for (int it = 0; it < KT; it++) {
        const int s = it & (NST - 1);
        asm volatile("cp.async.wait_group 2;" ::: "memory");
        __syncthreads();
        const uint32_t stg = sbase + (uint32_t)s * STG_B;
#pragma unroll
        for (int ks = 0; ks < 4; ks++) {             // 4 x k16 slices per 64-chunk
            uint32_t ah[4][4], al[4][4], b[4][2];
#pragma unroll
            for (int mt = 0; mt < 4; mt++) {
                ldm4(ah[mt], stg + OAHI + aoff + mt * (16 * RST) + ks * 32);
                ldm4(al[mt], stg + OALO + aoff + mt * (16 * RST) + ks * 32);
            }
#pragma unroll
            for (int ntp = 0; ntp < 2; ntp++) {
                uint32_t t[4];
                ldm4(t, stg + OBS + boff + ntp * (16 * RST) + ks * 32);
                b[2*ntp][0] = t[0]; b[2*ntp][1] = t[1];
                b[2*ntp+1][0] = t[2]; b[2*ntp+1][1] = t[3];
            }
#pragma unroll
            for (int mt = 0; mt < 4; mt++)
#pragma unroll
                for (int nt = 0; nt < 4; nt++) {
                    mma_f16(acc[mt][nt], ah[mt], b[nt][0], b[nt][1]);
                    mma_f16(acc[mt][nt], al[mt], b[nt][0], b[nt][1]);
                }
        }
        load_stage((it + 3) & (NST - 1), it + 3);
    }

    // ---- epilogue ----
    const int r0 = wm + (lane >> 2);
    const int c0 = wn + (lane & 3) * 2;
#pragma unroll
    for (int mt = 0; mt < 4; mt++) {
#pragma unroll
        for (int nt = 0; nt < 4; nt++) {
            const int row = m0 + r0 + mt * 16;
            const int col = n0 + c0 + nt * 8;
            const float v0 = acc[mt][nt][0] * alpha, v1 = acc[mt][nt][1] * alpha;
            const float v2 = acc[mt][nt][2] * alpha, v3 = acc[mt][nt][3] * alpha;
            if (EPI == 0) {
                float* d0 = Cf + (size_t)z * sC + (size_t)row * N + col;
                float* d1 = Cf + (size_t)z * sC + (size_t)(row + 8) * N + col;
                d0[0] = v0; d0[1] = v1;
                d1[0] = v2; d1[1] = v3;
            } else {
                const size_t o0 = (size_t)row * N + col;
                const size_t o1 = (size_t)(row + 8) * N + col;
                if (z == 0) {
                    h16 h0 = __float2half_rn(v0), h1 = __float2half_rn(v1);
                    h16 h2 = __float2half_rn(v2), h3 = __float2half_rn(v3);
                    h16 l0 = __float2half_rn(v0 - __half2float(h0));
                    h16 l1 = __float2half_rn(v1 - __half2float(h1));
                    h16 l2 = __float2half_rn(v2 - __half2float(h2));
                    h16 l3 = __float2half_rn(v3 - __half2float(h3));
                    *reinterpret_cast<uint32_t*>(Chi + o0) = pack2(h0, h1);
                    *reinterpret_cast<uint32_t*>(Chi + o1) = pack2(h2, h3);
                    *reinterpret_cast<uint32_t*>(Clo + o0) = pack2(l0, l1);
                    *reinterpret_cast<uint32_t*>(Clo + o1) = pack2(l2, l3);
                } else {
                    h16* dst = Cs + (size_t)(z - 1) * strCs;
                    *reinterpret_cast<uint32_t*>(dst + o0) =
                        pack2(__float2half_rn(v0), __float2half_rn(v1));
                    *reinterpret_cast<uint32_t*>(dst + o1) =
                        pack2(__float2half_rn(v2), __float2half_rn(v3));
                }
            }
        }
    }
}

// ---------------- conversion / transpose / softmax ----------------
__global__ __launch_bounds__(256) void split_x_kernel(
    const float* __restrict__ in, h16* __restrict__ hi, h16* __restrict__ lo, size_t n)
{
    for (size_t i = (size_t)blockIdx.x * 256 + threadIdx.x; i < n; i += (size_t)gridDim.x * 256) {
        const float v = in[i];
        const h16 h = __float2half_rn(v);
        hi[i] = h;
        lo[i] = __float2half_rn(v - __half2float(h));
    }
}

// W fp32 [D,D] -> W^T fp16 single [D,D]
__global__ void transpose_w_kernel(const float* __restrict__ W, h16* __restrict__ Wt)
{
    __shared__ float t[32][33];
    const int c0 = blockIdx.x * 32, r0 = blockIdx.y * 32;
    const int tx = threadIdx.x, ty = threadIdx.y;
#pragma unroll
    for (int j = 0; j < 32; j += 8)
        t[ty + j][tx] = W[(size_t)(r0 + ty + j) * DD + c0 + tx];
    __syncthreads();
#pragma unroll
    for (int j = 0; j < 32; j += 8)
        Wt[(size_t)(c0 + ty + j) * DD + r0 + tx] = __float2half_rn(t[tx][ty + j]);
}

// V fp16 [B,S,D] -> [B,D,S]
__global__ void transpose_v_kernel(const h16* __restrict__ V, h16* __restrict__ VT)
{
    __shared__ h16 t[32][33];
    const int b = blockIdx.z;
    const int d0 = blockIdx.x * 32, s0 = blockIdx.y * 32;
    const int tx = threadIdx.x, ty = threadIdx.y;
    const h16* s = V + (size_t)b * SS * DD;
    h16* d = VT + (size_t)b * DD * SS;
#pragma unroll
    for (int j = 0; j < 32; j += 8)
        t[ty + j][tx] = s[(size_t)(s0 + ty + j) * DD + d0 + tx];
    __syncthreads();
#pragma unroll
    for (int j = 0; j < 32; j += 8)
        d[(size_t)(d0 + ty + j) * SS + s0 + tx] = t[tx][ty + j];
}

// causal softmax over fp32 P rows -> split fp16
__global__ __launch_bounds__(256) void softmax_split_kernel(
    const float* __restrict__ P, h16* __restrict__ Phi, h16* __restrict__ Plo)
{
    const int row = blockIdx.x & (SS - 1);
    const int b   = blockIdx.x >> 11;
    const size_t base = ((size_t)b * SS + row) * SS;
    const int L = row + 1;
    const int tid = threadIdx.x;

    float v[8];
    float m = -INFINITY;
#pragma unroll
    for (int j = 0; j < 8; j++) {
        const int i = tid + j * 256;
        v[j] = (i < L) ? P[base + i] : -INFINITY;
        m = fmaxf(m, v[j]);
    }
    __shared__ float red[256];
    red[tid] = m; __syncthreads();
    for (int s2 = 128; s2 > 0; s2 >>= 1) {
        if (tid < s2) red[tid] = fmaxf(red[tid], red[tid + s2]);
        __syncthreads();
    }
    m = red[0]; __syncthreads();

    float sum = 0.0f;
#pragma unroll
    for (int j = 0; j < 8; j++) {
        const int i = tid + j * 256;
        if (i < L) { v[j] = __expf(v[j] - m); sum += v[j]; }
    }
    red[tid] = sum; __syncthreads();
    for (int s2 = 128; s2 > 0; s2 >>= 1) {
        if (tid < s2) red[tid] += red[tid + s2];
        __syncthreads();
    }
    const float inv = 1.0f / red[0];
    __syncthreads();

#pragma unroll
    for (int j = 0; j < 8; j++) {
        const int i = tid + j * 256;
        if (i < L) {
            const float val = v[j] * inv;
            const h16 h = __float2half_rn(val);
            Phi[base + i] = h;
            Plo[base + i] = __float2half_rn(val - __half2float(h));
        }
    }
    const h16 z16 = __float2half_rn(0.0f);
    for (int i = L + tid; i < SS; i += 256) { Phi[base + i] = z16; Plo[base + i] = z16; }
}

// ---------------- launch ----------------
extern "C" void kernel_launch(void* const* d_in, const int* in_sizes, int n_in,
                              void* d_out, int out_size)
{
    const float* x  = (const float*)d_in[0];
    const float* Wq = (const float*)d_in[1];
    const float* Wk = (const float*)d_in[2];
    const float* Wv = (const float*)d_in[3];
    float* out = (float*)d_out;

    h16 *xhi, *xlo, *Wt, *Qhi, *Qlo, *KV, *VT, *Phi, *Plo;
    float* P;
    cudaGetSymbolAddress((void**)&xhi, g_xhi);
    cudaGetSymbolAddress((void**)&xlo, g_xlo);
    cudaGetSymbolAddress((void**)&Wt,  g_Wt);
    cudaGetSymbolAddress((void**)&Qhi, g_Qhi);
    cudaGetSymbolAddress((void**)&Qlo, g_Qlo);
    cudaGetSymbolAddress((void**)&KV,  g_KV);
    cudaGetSymbolAddress((void**)&VT,  g_VT);
    cudaGetSymbolAddress((void**)&P,   g_P);
    cudaGetSymbolAddress((void**)&Phi, g_Phi);
    cudaGetSymbolAddress((void**)&Plo, g_Plo);

    cudaFuncSetAttribute(gemm_f16<1,0>, cudaFuncAttributeMaxDynamicSharedMemorySize, SMEM_G);
    cudaFuncSetAttribute(gemm_f16<0,1>, cudaFuncAttributeMaxDynamicSharedMemorySize, SMEM_G);
    cudaFuncSetAttribute(gemm_f16<0,2>, cudaFuncAttributeMaxDynamicSharedMemorySize, SMEM_G);

    const size_t WSZ = (size_t)DD * DD;
    const size_t QSZ = (size_t)BB * SS * DD;
    const dim3 t32(32, 8);

    // prep
    split_x_kernel<<<8192, 256>>>(x, xhi, xlo, QSZ);
    transpose_w_kernel<<<dim3(DD/32, DD/32), t32>>>(Wq, Wt + 0*WSZ);
    transpose_w_kernel<<<dim3(DD/32, DD/32), t32>>>(Wk, Wt + 1*WSZ);
    transpose_w_kernel<<<dim3(DD/32, DD/32), t32>>>(Wv, Wt + 2*WSZ);

    // QKV (fused z=3): z0 -> Qhi/Qlo split, z1 -> K single, z2 -> V single
    dim3 g1(DD/128, (BB*SS)/128, 3);
    gemm_f16<1,0><<<g1, 256, SMEM_G>>>(xhi, xlo, Wt,
                                       nullptr, Qhi, Qlo, KV,
                                       BB*SS, DD, DD, 0, WSZ, 0, QSZ, 1.0f);

    // V^T
    transpose_v_kernel<<<dim3(DD/32, SS/32, BB), t32>>>(KV + QSZ, VT);

    // scores: P[b] = scale * Q[b] @ K[b]^T (skip fully-masked tiles)
    dim3 g2(SS/128, SS/128, BB);
    const float scale = 1.0f / sqrtf((float)DD);
    gemm_f16<0,1><<<g2, 256, SMEM_G>>>(Qhi, Qlo, KV,
                                       P, nullptr, nullptr, nullptr,
                                       SS, SS, DD, (size_t)SS*DD, (size_t)SS*DD,
                                       (size_t)SS*SS, 0, scale);

    // causal softmax -> split fp16 P
    softmax_split_kernel<<<BB * SS, 256>>>(P, Phi, Plo);

    // out[b] = P[b] @ V[b] (K truncated at diagonal)
    dim3 g3(DD/128, SS/128, BB);
    gemm_f16<0,2><<<g3, 256, SMEM_G>>>(Phi, Plo, VT,
                                       out, nullptr, nullptr, nullptr,
                                       SS, DD, SS, (size_t)SS*SS, (size_t)SS*DD,
                                       (size_t)SS*DD, 0, 1.0f);
}

// round 7
// speedup vs baseline: 6.1702x; 1.6856x over previous
#include <cuda_runtime.h>
#include <cuda_fp16.h>
#include <cstdint>
#include <math.h>

#define BB 4
#define SS 2048
#define DD 2048
typedef __half h16;

// ---------------- scratch (static device globals; no allocs) ----------------
__device__ h16  g_x16[(size_t)BB*SS*DD];
__device__ h16  g_Wt[3][(size_t)DD*DD];
__device__ h16  g_QKV[3][(size_t)BB*SS*DD];
__device__ h16  g_VT[(size_t)BB*SS*DD];          // V^T [B,D,S]
__device__ float g_P[(size_t)BB*SS*SS];
__device__ h16  g_Ph[(size_t)BB*SS*SS];

// ---------------- helpers ----------------
__device__ __forceinline__ uint32_t smem_u32(const void* p) {
    uint32_t a;
    asm("{ .reg .u64 t; cvta.to.shared.u64 t, %1; cvt.u32.u64 %0, t; }" : "=r"(a) : "l"(p));
    return a;
}
__device__ __forceinline__ void cp16(uint32_t dst, const void* src) {
    asm volatile("cp.async.cg.shared.global [%0], [%1], 16;" :: "r"(dst), "l"(src));
}
__device__ __forceinline__ void ldm4(uint32_t* r, uint32_t addr) {
    asm volatile("ldmatrix.sync.aligned.m8n8.x4.shared.b16 {%0,%1,%2,%3}, [%4];"
                 : "=r"(r[0]), "=r"(r[1]), "=r"(r[2]), "=r"(r[3]) : "r"(addr));
}
__device__ __forceinline__ void mma_f16(float c[4], const uint32_t a[4],
                                        uint32_t b0, uint32_t b1) {
    asm volatile(
        "mma.sync.aligned.m16n8k16.row.col.f32.f16.f16.f32 "
        "{%0,%1,%2,%3}, {%4,%5,%6,%7}, {%8,%9}, {%0,%1,%2,%3};"
        : "+f"(c[0]), "+f"(c[1]), "+f"(c[2]), "+f"(c[3])
        : "r"(a[0]), "r"(a[1]), "r"(a[2]), "r"(a[3]), "r"(b0), "r"(b1));
}
__device__ __forceinline__ uint32_t pack2(h16 a, h16 b) {
    return (uint32_t)__half_as_ushort(a) | ((uint32_t)__half_as_ushort(b) << 16);
}

// ---------------- GEMM geometry: CTA 128x128, warp 64x32, BK=64, 4 stages ----
#define RST 144                      // 128B data + 16B pad
#define ARR_B (128 * RST)            // 18432
#define OA 0
#define OB ARR_B
#define STG_B (2 * ARR_B)            // 36864
#define NST 4
#define SMEM_G (NST * STG_B)         // 147456

// C[z] = alpha * A[z] @ B[z]^T   (single fp16 operands, fp32 accum)
// A: [M,K] rows; B: [N,K] rows (K-major).
// EPI 0: fp32 to Cf.  EPI 1: fp16 to Ch.
// MODE 0: dense. MODE 1: skip tiles fully above causal diag. MODE 2: K trunc at m0+128.
template<int EPI, int MODE>
__global__ void __launch_bounds__(256, 1)
gemm_f16(const h16* __restrict__ A, const h16* __restrict__ B,
         float* __restrict__ Cf, h16* __restrict__ Ch,
         int M, int N, int K, size_t sA, size_t sB, size_t sC, float alpha)
{
    const int m0 = blockIdx.y * 128;
    const int n0 = blockIdx.x * 128;
    const int z  = blockIdx.z;
    if (MODE == 1 && n0 > m0) return;
    int KT = K / 64;
    if (MODE == 2) { int kmax = m0 + 128; if (kmax < K) KT = kmax / 64; }

    extern __shared__ char smem[];
    const uint32_t sbase = smem_u32(smem);
    const int tid  = threadIdx.x;
    const int lane = tid & 31;
    const int wid  = tid >> 5;
    const int wm   = (wid >> 2) * 64;
    const int wn   = (wid & 3) * 32;

    const h16* pA = A + (size_t)z * sA;
    const h16* pB = B + (size_t)z * sB;

    auto load_stage = [&](int s, int kt) {
        if (kt < KT) {
            const uint32_t st = sbase + (uint32_t)s * STG_B;
            const size_t ko = (size_t)kt * 64;
#pragma unroll
            for (int i = 0; i < 4; i++) {
                const int slot = tid + i * 256;       // 0..1023
                const int row = slot >> 3;
                const int seg = slot & 7;
                const uint32_t so = (uint32_t)(row * RST + seg * 16);
                const size_t go = ko + seg * 8;
                cp16(st + OA + so, pA + (size_t)(m0 + row) * K + go);
                cp16(st + OB + so, pB + (size_t)(n0 + row) * K + go);
            }
        }
        asm volatile("cp.async.commit_group;" ::: "memory");
    };

    const int arow = lane & 15;
    const int akh  = lane >> 4;
    const int nrow = (lane & 7) + ((lane >> 4) << 3);
    const int bkh  = (lane >> 3) & 1;
    const uint32_t aoff = (uint32_t)((wm + arow) * RST + akh * 16);
    const uint32_t boff = (uint32_t)((wn + nrow) * RST + bkh * 16);

    float acc[4][4][4];
#pragma unroll
    for (int i = 0; i < 4; i++)
#pragma unroll
        for (int j = 0; j < 4; j++)
#pragma unroll
            for (int q = 0; q < 4; q++) acc[i][j][q] = 0.0f;

    load_stage(0, 0);
    load_stage(1, 1);
    load_stage(2, 2);

    for (int it = 0; it < KT; it++) {
        const int s = it & (NST - 1);
        asm volatile("cp.async.wait_group 2;" ::: "memory");
        __syncthreads();
        const uint32_t stg = sbase + (uint32_t)s * STG_B;
#pragma unroll
        for (int ks = 0; ks < 4; ks++) {             // 4 x k16 slices per 64-chunk
            uint32_t a[4][4], b[4][2];
#pragma unroll
            for (int mt = 0; mt < 4; mt++)
                ldm4(a[mt], stg + OA + aoff + mt * (16 * RST) + ks * 32);
#pragma unroll
            for (int ntp = 0; ntp < 2; ntp++) {
                uint32_t t[4];
                ldm4(t, stg + OB + boff + ntp * (16 * RST) + ks * 32);
                b[2*ntp][0] = t[0]; b[2*ntp][1] = t[1];
                b[2*ntp+1][0] = t[2]; b[2*ntp+1][1] = t[3];
            }
#pragma unroll
            for (int mt = 0; mt < 4; mt++)
#pragma unroll
                for (int nt = 0; nt < 4; nt++)
                    mma_f16(acc[mt][nt], a[mt], b[nt][0], b[nt][1]);
        }
        load_stage((it + 3) & (NST - 1), it + 3);
    }

    // ---- epilogue ----
    const int r0 = wm + (lane >> 2);
    const int c0 = wn + (lane & 3) * 2;
#pragma unroll
    for (int mt = 0; mt < 4; mt++) {
#pragma unroll
        for (int nt = 0; nt < 4; nt++) {
            const int row = m0 + r0 + mt * 16;
            const int col = n0 + c0 + nt * 8;
            const float v0 = acc[mt][nt][0] * alpha, v1 = acc[mt][nt][1] * alpha;
            const float v2 = acc[mt][nt][2] * alpha, v3 = acc[mt][nt][3] * alpha;
            const size_t o0 = (size_t)z * sC + (size_t)row * N + col;
            const size_t o1 = (size_t)z * sC + (size_t)(row + 8) * N + col;
            if (EPI == 0) {
                Cf[o0] = v0; Cf[o0 + 1] = v1;
                Cf[o1] = v2; Cf[o1 + 1] = v3;
            } else {
                *reinterpret_cast<uint32_t*>(Ch + o0) =
                    pack2(__float2half_rn(v0), __float2half_rn(v1));
                *reinterpret_cast<uint32_t*>(Ch + o1) =
                    pack2(__float2half_rn(v2), __float2half_rn(v3));
            }
        }
    }
}

// ---------------- conversion / transpose / softmax ----------------
__global__ __launch_bounds__(256) void convert_x_kernel(
    const float* __restrict__ in, h16* __restrict__ out, size_t n4)
{
    // n4 = n/4; vectorized
    for (size_t i = (size_t)blockIdx.x * 256 + threadIdx.x; i < n4; i += (size_t)gridDim.x * 256) {
        const float4 v = reinterpret_cast<const float4*>(in)[i];
        uint2 o;
        o.x = pack2(__float2half_rn(v.x), __float2half_rn(v.y));
        o.y = pack2(__float2half_rn(v.z), __float2half_rn(v.w));
        reinterpret_cast<uint2*>(out)[i] = o;
    }
}

// W fp32 [D,D] -> W^T fp16 [D,D]; grid.z selects which W
__global__ void transpose_w_kernel(const float* __restrict__ W0,
                                   const float* __restrict__ W1,
                                   const float* __restrict__ W2,
                                   h16* __restrict__ Wt)
{
    __shared__ float t[32][33];
    const float* W = (blockIdx.z == 0) ? W0 : (blockIdx.z == 1) ? W1 : W2;
    h16* dst = Wt + (size_t)blockIdx.z * DD * DD;
    const int c0 = blockIdx.x * 32, r0 = blockIdx.y * 32;
    const int tx = threadIdx.x, ty = threadIdx.y;
#pragma unroll
    for (int j = 0; j < 32; j += 8)
        t[ty + j][tx] = W[(size_t)(r0 + ty + j) * DD + c0 + tx];
    __syncthreads();
#pragma unroll
    for (int j = 0; j < 32; j += 8)
        dst[(size_t)(c0 + ty + j) * DD + r0 + tx] = __float2half_rn(t[tx][ty + j]);
}

// V fp16 [B,S,D] -> [B,D,S]
__global__ void transpose_v_kernel(const h16* __restrict__ V, h16* __restrict__ VT)
{
    __shared__ h16 t[32][33];
    const int b = blockIdx.z;
    const int d0 = blockIdx.x * 32, s0 = blockIdx.y * 32;
    const int tx = threadIdx.x, ty = threadIdx.y;
    const h16* s = V + (size_t)b * SS * DD;
    h16* d = VT + (size_t)b * DD * SS;
#pragma unroll
    for (int j = 0; j < 32; j += 8)
        t[ty + j][tx] = s[(size_t)(s0 + ty + j) * DD + d0 + tx];
    __syncthreads();
#pragma unroll
    for (int j = 0; j < 32; j += 8)
        d[(size_t)(d0 + ty + j) * SS + s0 + tx] = t[tx][ty + j];
}

// causal softmax over fp32 P rows -> single fp16
__global__ __launch_bounds__(256) void softmax_kernel(
    const float* __restrict__ P, h16* __restrict__ Ph)
{
    const int row = blockIdx.x & (SS - 1);
    const int b   = blockIdx.x >> 11;
    const size_t base = ((size_t)b * SS + row) * SS;
    const int L = row + 1;
    const int tid = threadIdx.x;

    float v[8];
    float m = -INFINITY;
#pragma unroll
    for (int j = 0; j < 8; j++) {
        const int i = tid + j * 256;
        v[j] = (i < L) ? P[base + i] : -INFINITY;
        m = fmaxf(m, v[j]);
    }
    __shared__ float red[256];
    red[tid] = m; __syncthreads();
    for (int s2 = 128; s2 > 0; s2 >>= 1) {
        if (tid < s2) red[tid] = fmaxf(red[tid], red[tid + s2]);
        __syncthreads();
    }
    m = red[0]; __syncthreads();

    float sum = 0.0f;
#pragma unroll
    for (int j = 0; j < 8; j++) {
        const int i = tid + j * 256;
        if (i < L) { v[j] = __expf(v[j] - m); sum += v[j]; }
    }
    red[tid] = sum; __syncthreads();
    for (int s2 = 128; s2 > 0; s2 >>= 1) {
        if (tid < s2) red[tid] += red[tid + s2];
        __syncthreads();
    }
    const float inv = 1.0f / red[0];
    __syncthreads();

#pragma unroll
    for (int j = 0; j < 8; j++) {
        const int i = tid + j * 256;
        if (i < L) Ph[base + i] = __float2half_rn(v[j] * inv);
    }
    const h16 z16 = __ushort_as_half(0);
    for (int i = L + tid; i < SS; i += 256) Ph[base + i] = z16;
}

// ---------------- launch ----------------
extern "C" void kernel_launch(void* const* d_in, const int* in_sizes, int n_in,
                              void* d_out, int out_size)
{
    const float* x  = (const float*)d_in[0];
    const float* Wq = (const float*)d_in[1];
    const float* Wk = (const float*)d_in[2];
    const float* Wv = (const float*)d_in[3];
    float* out = (float*)d_out;

    h16 *x16, *Wt, *QKV, *VT, *Ph;
    float* P;
    cudaGetSymbolAddress((void**)&x16, g_x16);
    cudaGetSymbolAddress((void**)&Wt,  g_Wt);
    cudaGetSymbolAddress((void**)&QKV, g_QKV);
    cudaGetSymbolAddress((void**)&VT,  g_VT);
    cudaGetSymbolAddress((void**)&P,   g_P);
    cudaGetSymbolAddress((void**)&Ph,  g_Ph);

    cudaFuncSetAttribute(gemm_f16<1,0>, cudaFuncAttributeMaxDynamicSharedMemorySize, SMEM_G);
    cudaFuncSetAttribute(gemm_f16<0,1>, cudaFuncAttributeMaxDynamicSharedMemorySize, SMEM_G);
    cudaFuncSetAttribute(gemm_f16<0,2>, cudaFuncAttributeMaxDynamicSharedMemorySize, SMEM_G);

    const size_t WSZ = (size_t)DD * DD;
    const size_t QSZ = (size_t)BB * SS * DD;
    const dim3 t32(32, 8);

    // prep
    convert_x_kernel<<<4096, 256>>>(x, x16, QSZ / 4);
    transpose_w_kernel<<<dim3(DD/32, DD/32, 3), t32>>>(Wq, Wk, Wv, Wt);

    // QKV (fused z=3): single fp16 out
    dim3 g1(DD/128, (BB*SS)/128, 3);
    gemm_f16<1,0><<<g1, 256, SMEM_G>>>(x16, Wt, nullptr, QKV,
                                       BB*SS, DD, DD, 0, WSZ, QSZ, 1.0f);

    // V^T
    transpose_v_kernel<<<dim3(DD/32, SS/32, BB), t32>>>(QKV + 2*QSZ, VT);

    // scores: P[b] = scale * Q[b] @ K[b]^T (skip fully-masked tiles)
    dim3 g2(SS/128, SS/128, BB);
    const float scale = 1.0f / sqrtf((float)DD);
    gemm_f16<0,1><<<g2, 256, SMEM_G>>>(QKV, QKV + QSZ, P, nullptr,
                                       SS, SS, DD, (size_t)SS*DD, (size_t)SS*DD,
                                       (size_t)SS*SS, scale);

    // causal softmax -> fp16 P
    softmax_kernel<<<BB * SS, 256>>>(P, Ph);

    // out[b] = P[b] @ V[b] (K truncated at diagonal)
    dim3 g3(DD/128, SS/128, BB);
    gemm_f16<0,2><<<g3, 256, SMEM_G>>>(Ph, VT, out, nullptr,
                                       SS, DD, SS, (size_t)SS*SS, (size_t)SS*DD,
                                       (size_t)SS*DD, 1.0f);
}

// round 8
// speedup vs baseline: 6.2362x; 1.0107x over previous
#include <cuda_runtime.h>
#include <cuda_fp16.h>
#include <cstdint>
#include <math.h>

#define BB 4
#define SS 2048
#define DD 2048
#define XR (BB * SS)
typedef __half h16;

// ---------------- scratch ----------------
__device__ h16  g_x16[(size_t)XR*DD];
__device__ h16  g_w16[3][(size_t)DD*DD];         // fp16 W, natural [K,N]
__device__ h16  g_QKV[3][(size_t)XR*DD];
__device__ float g_P[(size_t)BB*SS*SS];
__device__ h16  g_Ph[(size_t)BB*SS*SS];

// ---------------- helpers ----------------
__device__ __forceinline__ uint32_t smem_u32(const void* p) {
    uint32_t a;
    asm("{ .reg .u64 t; cvta.to.shared.u64 t, %1; cvt.u32.u64 %0, t; }" : "=r"(a) : "l"(p));
    return a;
}
__device__ __forceinline__ void cp16(uint32_t dst, const void* src) {
    asm volatile("cp.async.cg.shared.global [%0], [%1], 16;" :: "r"(dst), "l"(src));
}
__device__ __forceinline__ void ldm4(uint32_t* r, uint32_t addr) {
    asm volatile("ldmatrix.sync.aligned.m8n8.x4.shared.b16 {%0,%1,%2,%3}, [%4];"
                 : "=r"(r[0]), "=r"(r[1]), "=r"(r[2]), "=r"(r[3]) : "r"(addr));
}
__device__ __forceinline__ void ldm4t(uint32_t* r, uint32_t addr) {
    asm volatile("ldmatrix.sync.aligned.m8n8.x4.trans.shared.b16 {%0,%1,%2,%3}, [%4];"
                 : "=r"(r[0]), "=r"(r[1]), "=r"(r[2]), "=r"(r[3]) : "r"(addr));
}
__device__ __forceinline__ void mma_f16(float c[4], const uint32_t a[4],
                                        uint32_t b0, uint32_t b1) {
    asm volatile(
        "mma.sync.aligned.m16n8k16.row.col.f32.f16.f16.f32 "
        "{%0,%1,%2,%3}, {%4,%5,%6,%7}, {%8,%9}, {%0,%1,%2,%3};"
        : "+f"(c[0]), "+f"(c[1]), "+f"(c[2]), "+f"(c[3])
        : "r"(a[0]), "r"(a[1]), "r"(a[2]), "r"(a[3]), "r"(b0), "r"(b1));
}
__device__ __forceinline__ uint32_t pack2(h16 a, h16 b) {
    return (uint32_t)__half_as_ushort(a) | ((uint32_t)__half_as_ushort(b) << 16);
}

// ---------------- GEMM geometry: CTA 128x128, warp 64x32, BK=64, 4 stages ----
#define RST 144                       // A row: 128B data + 16B pad
#define RSTB 272                      // trans-B row: 256B data + 16B pad
#define A_B (128 * RST)               // 18432
#define OB_OFF A_B
#define STG_NT (2 * A_B)              // 36864  (B as [N,K], 128 rows x 144B)
#define STG_TR (A_B + 64 * RSTB)      // 35840  (B as [K,N], 64 rows x 272B)
#define NST 4
#define SMEM_G (NST * STG_NT)         // 147456 (covers both variants)

// C[z] = alpha * A[z] @ op(B[z]);  A: [M,K] rows fp16.
// BTRANS=0: B is [N,K] rows (K-major). BTRANS=1: B is [K,N] rows, trans-ldmatrix.
// EPI 0: fp32 to Cf.  EPI 1: fp16 to Ch.
// MODE 0: dense. MODE 1: causal skip (n0 > m0). MODE 2: K truncated at m0+128.
// MODE 1/2 reverse blockIdx.y so heavy tiles launch first.
template<int EPI, int MODE, int BTRANS>
__global__ void __launch_bounds__(256, 1)
gemm_f16(const h16* __restrict__ A, const h16* __restrict__ B,
         float* __restrict__ Cf, h16* __restrict__ Ch,
         int M, int N, int K, size_t sA, size_t sB, size_t sC, float alpha)
{
    constexpr int STG_B = BTRANS ? STG_TR : STG_NT;
    int by = blockIdx.y;
    if (MODE == 1 || MODE == 2) by = gridDim.y - 1 - by;
    const int m0 = by * 128;
    const int n0 = blockIdx.x * 128;
    const int z  = blockIdx.z;
    if (MODE == 1 && n0 > m0) return;
    int KT = K / 64;
    if (MODE == 2) { int kmax = m0 + 128; if (kmax < K) KT = kmax / 64; }

    extern __shared__ char smem[];
    const uint32_t sbase = smem_u32(smem);
    const int tid  = threadIdx.x;
    const int lane = tid & 31;
    const int wid  = tid >> 5;
    const int wm   = (wid >> 2) * 64;
    const int wn   = (wid & 3) * 32;

    const h16* pA = A + (size_t)z * sA;
    const h16* pB = B + (size_t)z * sB;

    auto load_stage = [&](int s, int kt) {
        if (kt < KT) {
            const uint32_t st = sbase + (uint32_t)s * STG_B;
            const size_t k0 = (size_t)kt * 64;
#pragma unroll
            for (int i = 0; i < 4; i++) {          // A: 128 rows x 8 segs
                const int slot = tid + i * 256;
                const int row = slot >> 3;
                const int seg = slot & 7;
                cp16(st + (uint32_t)(row * RST + seg * 16),
                     pA + (size_t)(m0 + row) * K + k0 + seg * 8);
            }
            if (BTRANS) {
#pragma unroll
                for (int i = 0; i < 4; i++) {      // B: 64 k-rows x 16 segs
                    const int slot = tid + i * 256;
                    const int row = slot >> 4;
                    const int seg = slot & 15;
                    cp16(st + OB_OFF + (uint32_t)(row * RSTB + seg * 16),
                         pB + (k0 + row) * (size_t)N + n0 + seg * 8);
                }
            } else {
#pragma unroll
                for (int i = 0; i < 4; i++) {      // B: 128 n-rows x 8 segs
                    const int slot = tid + i * 256;
                    const int row = slot >> 3;
                    const int seg = slot & 7;
                    cp16(st + OB_OFF + (uint32_t)(row * RST + seg * 16),
                         pB + (size_t)(n0 + row) * K + k0 + seg * 8);
                }
            }
        }
        asm volatile("cp.async.commit_group;" ::: "memory");
    };

    // ldmatrix lane addressing
    const int arow = lane & 15;
    const int akh  = lane >> 4;
    const uint32_t aoff = (uint32_t)((wm + arow) * RST + akh * 16);
    // non-trans B
    const int nrow = (lane & 7) + ((lane >> 4) << 3);
    const int bkh  = (lane >> 3) & 1;
    const uint32_t boffN = (uint32_t)((wn + nrow) * RST + bkh * 16);
    // trans B: rows = k, 16B col = n-octet
    const int btrow = (lane & 7) + (((lane >> 3) & 1) << 3);
    const uint32_t boffT = (uint32_t)(btrow * RSTB + (((lane >> 4) << 3) + wn) * 2);

    float acc[4][4][4];
#pragma unroll
    for (int i = 0; i < 4; i++)
#pragma unroll
        for (int j = 0; j < 4; j++)
#pragma unroll
            for (int q = 0; q < 4; q++) acc[i][j][q] = 0.0f;

    load_stage(0, 0);
    load_stage(1, 1);
    load_stage(2, 2);

    for (int it = 0; it < KT; it++) {
        const int s = it & (NST - 1);
        asm volatile("cp.async.wait_group 2;" ::: "memory");
        __syncthreads();
        const uint32_t stg = sbase + (uint32_t)s * STG_B;
#pragma unroll
        for (int ks = 0; ks < 4; ks++) {
            uint32_t a[4][4], b[4][2];
#pragma unroll
            for (int mt = 0; mt < 4; mt++)
                ldm4(a[mt], stg + aoff + mt * (16 * RST) + ks * 32);
#pragma unroll
            for (int ntp = 0; ntp < 2; ntp++) {
                uint32_t t[4];
                if (BTRANS)
                    ldm4t(t, stg + OB_OFF + boffT + ks * (16 * RSTB) + ntp * 32);
                else
                    ldm4(t, stg + OB_OFF + boffN + ntp * (16 * RST) + ks * 32);
                b[2*ntp][0] = t[0]; b[2*ntp][1] = t[1];
                b[2*ntp+1][0] = t[2]; b[2*ntp+1][1] = t[3];
            }
#pragma unroll
            for (int mt = 0; mt < 4; mt++)
#pragma unroll
                for (int nt = 0; nt < 4; nt++)
                    mma_f16(acc[mt][nt], a[mt], b[nt][0], b[nt][1]);
        }
        load_stage((it + 3) & (NST - 1), it + 3);
    }

    // ---- epilogue ----
    const int r0 = wm + (lane >> 2);
    const int c0 = wn + (lane & 3) * 2;
#pragma unroll
    for (int mt = 0; mt < 4; mt++) {
#pragma unroll
        for (int nt = 0; nt < 4; nt++) {
            const int row = m0 + r0 + mt * 16;
            const int col = n0 + c0 + nt * 8;
            const float v0 = acc[mt][nt][0] * alpha, v1 = acc[mt][nt][1] * alpha;
            const float v2 = acc[mt][nt][2] * alpha, v3 = acc[mt][nt][3] * alpha;
            const size_t o0 = (size_t)z * sC + (size_t)row * N + col;
            const size_t o1 = (size_t)z * sC + (size_t)(row + 8) * N + col;
            if (EPI == 0) {
                Cf[o0] = v0; Cf[o0 + 1] = v1;
                Cf[o1] = v2; Cf[o1 + 1] = v3;
            } else {
                *reinterpret_cast<uint32_t*>(Ch + o0) =
                    pack2(__float2half_rn(v0), __float2half_rn(v1));
                *reinterpret_cast<uint32_t*>(Ch + o1) =
                    pack2(__float2half_rn(v2), __float2half_rn(v3));
            }
        }
    }
}

// ---------------- conversion (x + 3 W fused) / softmax ----------------
__global__ __launch_bounds__(256) void convert_all_kernel(
    const float* __restrict__ x, const float* __restrict__ W0,
    const float* __restrict__ W1, const float* __restrict__ W2,
    h16* __restrict__ x16, h16* __restrict__ w16)
{
    const int zz = blockIdx.z;
    const float* in;
    h16* out;
    size_t n4;
    if (zz == 0) { in = x;  out = x16;                          n4 = (size_t)XR * DD / 4; }
    else {
        in  = (zz == 1) ? W0 : (zz == 2) ? W1 : W2;
        out = w16 + (size_t)(zz - 1) * DD * DD;
        n4  = (size_t)DD * DD / 4;
    }
    for (size_t i = (size_t)blockIdx.x * 256 + threadIdx.x; i < n4; i += (size_t)gridDim.x * 256) {
        const float4 v = reinterpret_cast<const float4*>(in)[i];
        uint2 o;
        o.x = pack2(__float2half_rn(v.x), __float2half_rn(v.y));
        o.y = pack2(__float2half_rn(v.z), __float2half_rn(v.w));
        reinterpret_cast<uint2*>(out)[i] = o;
    }
}

__global__ __launch_bounds__(256) void softmax_kernel(
    const float* __restrict__ P, h16* __restrict__ Ph)
{
    const int row = blockIdx.x & (SS - 1);
    const int b   = blockIdx.x >> 11;
    const size_t base = ((size_t)b * SS + row) * SS;
    const int L = row + 1;
    const int tid = threadIdx.x;

    float v[8];
    float m = -INFINITY;
#pragma unroll
    for (int j = 0; j < 8; j++) {
        const int i = tid + j * 256;
        v[j] = (i < L) ? P[base + i] : -INFINITY;
        m = fmaxf(m, v[j]);
    }
    __shared__ float red[256];
    red[tid] = m; __syncthreads();
    for (int s2 = 128; s2 > 0; s2 >>= 1) {
        if (tid < s2) red[tid] = fmaxf(red[tid], red[tid + s2]);
        __syncthreads();
    }
    m = red[0]; __syncthreads();

    float sum = 0.0f;
#pragma unroll
    for (int j = 0; j < 8; j++) {
        const int i = tid + j * 256;
        if (i < L) { v[j] = __expf(v[j] - m); sum += v[j]; }
    }
    red[tid] = sum; __syncthreads();
    for (int s2 = 128; s2 > 0; s2 >>= 1) {
        if (tid < s2) red[tid] += red[tid + s2];
        __syncthreads();
    }
    const float inv = 1.0f / red[0];
    __syncthreads();

#pragma unroll
    for (int j = 0; j < 8; j++) {
        const int i = tid + j * 256;
        if (i < L) Ph[base + i] = __float2half_rn(v[j] * inv);
    }
    const h16 z16 = __ushort_as_half(0);
    for (int i = L + tid; i < SS; i += 256) Ph[base + i] = z16;
}

// ---------------- launch ----------------
extern "C" void kernel_launch(void* const* d_in, const int* in_sizes, int n_in,
                              void* d_out, int out_size)
{
    const float* x  = (const float*)d_in[0];
    const float* Wq = (const float*)d_in[1];
    const float* Wk = (const float*)d_in[2];
    const float* Wv = (const float*)d_in[3];
    float* out = (float*)d_out;

    h16 *x16, *w16, *QKV, *Ph;
    float* P;
    cudaGetSymbolAddress((void**)&x16, g_x16);
    cudaGetSymbolAddress((void**)&w16, g_w16);
    cudaGetSymbolAddress((void**)&QKV, g_QKV);
    cudaGetSymbolAddress((void**)&P,   g_P);
    cudaGetSymbolAddress((void**)&Ph,  g_Ph);

    cudaFuncSetAttribute(gemm_f16<1,0,1>, cudaFuncAttributeMaxDynamicSharedMemorySize, SMEM_G);
    cudaFuncSetAttribute(gemm_f16<0,1,0>, cudaFuncAttributeMaxDynamicSharedMemorySize, SMEM_G);
    cudaFuncSetAttribute(gemm_f16<0,2,1>, cudaFuncAttributeMaxDynamicSharedMemorySize, SMEM_G);

    const size_t WSZ = (size_t)DD * DD;
    const size_t QSZ = (size_t)XR * DD;

    // fp32 -> fp16 conversions (x and W in natural layouts)
    convert_all_kernel<<<dim3(2048, 1, 4), 256>>>(x, Wq, Wk, Wv, x16, w16);

    // QKV (fused z=3): A = x16 [M,K]; B = w16 [K,N] via trans-ldmatrix
    dim3 g1(DD/128, XR/128, 3);
    gemm_f16<1,0,1><<<g1, 256, SMEM_G>>>(x16, w16, nullptr, QKV,
                                         XR, DD, DD, 0, WSZ, QSZ, 1.0f);

    // scores: P[b] = scale * Q[b] @ K[b]^T  (K is [N,K] natural; causal skip)
    dim3 g2(SS/128, SS/128, BB);
    const float scale = 1.0f / sqrtf((float)DD);
    gemm_f16<0,1,0><<<g2, 256, SMEM_G>>>(QKV, QKV + QSZ, P, nullptr,
                                         SS, SS, DD, (size_t)SS*DD, (size_t)SS*DD,
                                         (size_t)SS*SS, scale);

    // causal softmax -> fp16 P
    softmax_kernel<<<BB * SS, 256>>>(P, Ph);

    // out[b] = P[b] @ V[b]: A = Ph [M,K]; B = V [K,N] natural via trans-ldmatrix
    dim3 g3(DD/128, SS/128, BB);
    gemm_f16<0,2,1><<<g3, 256, SMEM_G>>>(Ph, QKV + 2*QSZ, out, nullptr,
                                         SS, DD, SS, (size_t)SS*SS, (size_t)SS*DD,
                                         (size_t)SS*DD, 1.0f);
}

// round 9
// speedup vs baseline: 6.5444x; 1.0494x over previous
#include <cuda_runtime.h>
#include <cuda_fp16.h>
#include <cstdint>
#include <math.h>

#define BB 4
#define SS 2048
#define DD 2048
#define XR (BB * SS)
typedef __half h16;

// ---------------- scratch ----------------
__device__ h16  g_x16[(size_t)XR*DD];
__device__ h16  g_w16[3][(size_t)DD*DD];         // fp16 W, natural [K,N]
__device__ h16  g_QKV[3][(size_t)XR*DD];
__device__ float g_P[(size_t)BB*SS*SS];
__device__ h16  g_Ph[(size_t)BB*SS*SS];

// ---------------- helpers ----------------
__device__ __forceinline__ uint32_t smem_u32(const void* p) {
    uint32_t a;
    asm("{ .reg .u64 t; cvta.to.shared.u64 t, %1; cvt.u32.u64 %0, t; }" : "=r"(a) : "l"(p));
    return a;
}
__device__ __forceinline__ void cp16(uint32_t dst, const void* src) {
    asm volatile("cp.async.cg.shared.global [%0], [%1], 16;" :: "r"(dst), "l"(src));
}
__device__ __forceinline__ void ldm4(uint32_t* r, uint32_t addr) {
    asm volatile("ldmatrix.sync.aligned.m8n8.x4.shared.b16 {%0,%1,%2,%3}, [%4];"
                 : "=r"(r[0]), "=r"(r[1]), "=r"(r[2]), "=r"(r[3]) : "r"(addr));
}
__device__ __forceinline__ void ldm4t(uint32_t* r, uint32_t addr) {
    asm volatile("ldmatrix.sync.aligned.m8n8.x4.trans.shared.b16 {%0,%1,%2,%3}, [%4];"
                 : "=r"(r[0]), "=r"(r[1]), "=r"(r[2]), "=r"(r[3]) : "r"(addr));
}
__device__ __forceinline__ void mma_f16(float c[4], const uint32_t a[4],
                                        uint32_t b0, uint32_t b1) {
    asm volatile(
        "mma.sync.aligned.m16n8k16.row.col.f32.f16.f16.f32 "
        "{%0,%1,%2,%3}, {%4,%5,%6,%7}, {%8,%9}, {%0,%1,%2,%3};"
        : "+f"(c[0]), "+f"(c[1]), "+f"(c[2]), "+f"(c[3])
        : "r"(a[0]), "r"(a[1]), "r"(a[2]), "r"(a[3]), "r"(b0), "r"(b1));
}
__device__ __forceinline__ uint32_t pack2(h16 a, h16 b) {
    return (uint32_t)__half_as_ushort(a) | ((uint32_t)__half_as_ushort(b) << 16);
}

// ---------------- GEMM geometry: CTA 128x128, warp 64x32, BK=64, 3 stages ----
#define RST 144                       // A row: 128B data + 16B pad
#define RSTB 272                      // trans-B row: 256B data + 16B pad
#define A_B (128 * RST)               // 18432
#define OB_OFF A_B
#define STG_NT (2 * A_B)              // 36864  (B as [N,K], 128 rows x 144B)
#define STG_TR (A_B + 64 * RSTB)      // 35840  (B as [K,N], 64 rows x 272B)
#define NST 3
#define SMEM_G (NST * STG_NT)         // 110592 -> 2 CTAs/SM

// C[z] = alpha * A[z] @ op(B[z]);  A: [M,K] rows fp16.
// BTRANS=0: B is [N,K] rows (K-major). BTRANS=1: B is [K,N] rows, trans-ldmatrix.
// EPI 0: fp32 to Cf.  EPI 1: fp16 to Ch.
// MODE 0: dense. MODE 1: causal skip (n0 > m0). MODE 2: K truncated at m0+128.
// MODE 1/2 reverse blockIdx.y so heavy tiles launch first.
template<int EPI, int MODE, int BTRANS>
__global__ void __launch_bounds__(256, 2)
gemm_f16(const h16* __restrict__ A, const h16* __restrict__ B,
         float* __restrict__ Cf, h16* __restrict__ Ch,
         int M, int N, int K, size_t sA, size_t sB, size_t sC, float alpha)
{
    constexpr int STG_B = BTRANS ? STG_TR : STG_NT;
    int by = blockIdx.y;
    if (MODE == 1 || MODE == 2) by = gridDim.y - 1 - by;
    const int m0 = by * 128;
    const int n0 = blockIdx.x * 128;
    const int z  = blockIdx.z;
    if (MODE == 1 && n0 > m0) return;
    int KT = K / 64;
    if (MODE == 2) { int kmax = m0 + 128; if (kmax < K) KT = kmax / 64; }

    extern __shared__ char smem[];
    const uint32_t sbase = smem_u32(smem);
    const int tid  = threadIdx.x;
    const int lane = tid & 31;
    const int wid  = tid >> 5;
    const int wm   = (wid >> 2) * 64;
    const int wn   = (wid & 3) * 32;

    const h16* pA = A + (size_t)z * sA;
    const h16* pB = B + (size_t)z * sB;

    auto load_stage = [&](int s, int kt) {
        if (kt < KT) {
            const uint32_t st = sbase + (uint32_t)s * STG_B;
            const size_t k0 = (size_t)kt * 64;
#pragma unroll
            for (int i = 0; i < 4; i++) {          // A: 128 rows x 8 segs
                const int slot = tid + i * 256;
                const int row = slot >> 3;
                const int seg = slot & 7;
                cp16(st + (uint32_t)(row * RST + seg * 16),
                     pA + (size_t)(m0 + row) * K + k0 + seg * 8);
            }
            if (BTRANS) {
#pragma unroll
                for (int i = 0; i < 4; i++) {      // B: 64 k-rows x 16 segs
                    const int slot = tid + i * 256;
                    const int row = slot >> 4;
                    const int seg = slot & 15;
                    cp16(st + OB_OFF + (uint32_t)(row * RSTB + seg * 16),
                         pB + (k0 + row) * (size_t)N + n0 + seg * 8);
                }
            } else {
#pragma unroll
                for (int i = 0; i < 4; i++) {      // B: 128 n-rows x 8 segs
                    const int slot = tid + i * 256;
                    const int row = slot >> 3;
                    const int seg = slot & 7;
                    cp16(st + OB_OFF + (uint32_t)(row * RST + seg * 16),
                         pB + (size_t)(n0 + row) * K + k0 + seg * 8);
                }
            }
        }
        asm volatile("cp.async.commit_group;" ::: "memory");
    };

    // ldmatrix lane addressing
    const int arow = lane & 15;
    const int akh  = lane >> 4;
    const uint32_t aoff = (uint32_t)((wm + arow) * RST + akh * 16);
    // non-trans B
    const int nrow = (lane & 7) + ((lane >> 4) << 3);
    const int bkh  = (lane >> 3) & 1;
    const uint32_t boffN = (uint32_t)((wn + nrow) * RST + bkh * 16);
    // trans B: rows = k, 16B col = n-octet
    const int btrow = (lane & 7) + (((lane >> 3) & 1) << 3);
    const uint32_t boffT = (uint32_t)(btrow * RSTB + (((lane >> 4) << 3) + wn) * 2);

    float acc[4][4][4];
#pragma unroll
    for (int i = 0; i < 4; i++)
#pragma unroll
        for (int j = 0; j < 4; j++)
#pragma unroll
            for (int q = 0; q < 4; q++) acc[i][j][q] = 0.0f;

    load_stage(0, 0);
    load_stage(1, 1);

    for (int it = 0; it < KT; it++) {
        const int s = it % NST;
        asm volatile("cp.async.wait_group 1;" ::: "memory");
        __syncthreads();
        const uint32_t stg = sbase + (uint32_t)s * STG_B;
#pragma unroll
        for (int ks = 0; ks < 4; ks++) {
            uint32_t a[4][4], b[4][2];
#pragma unroll
            for (int mt = 0; mt < 4; mt++)
                ldm4(a[mt], stg + aoff + mt * (16 * RST) + ks * 32);
#pragma unroll
            for (int ntp = 0; ntp < 2; ntp++) {
                uint32_t t[4];
                if (BTRANS)
                    ldm4t(t, stg + OB_OFF + boffT + ks * (16 * RSTB) + ntp * 32);
                else
                    ldm4(t, stg + OB_OFF + boffN + ntp * (16 * RST) + ks * 32);
                b[2*ntp][0] = t[0]; b[2*ntp][1] = t[1];
                b[2*ntp+1][0] = t[2]; b[2*ntp+1][1] = t[3];
            }
#pragma unroll
            for (int mt = 0; mt < 4; mt++)
#pragma unroll
                for (int nt = 0; nt < 4; nt++)
                    mma_f16(acc[mt][nt], a[mt], b[nt][0], b[nt][1]);
        }
        __syncthreads();                 // stage s fully consumed before overwrite
        load_stage((it + 2) % NST, it + 2);
    }

    // ---- epilogue ----
    const int r0 = wm + (lane >> 2);
    const int c0 = wn + (lane & 3) * 2;
#pragma unroll
    for (int mt = 0; mt < 4; mt++) {
#pragma unroll
        for (int nt = 0; nt < 4; nt++) {
            const int row = m0 + r0 + mt * 16;
            const int col = n0 + c0 + nt * 8;
            const float v0 = acc[mt][nt][0] * alpha, v1 = acc[mt][nt][1] * alpha;
            const float v2 = acc[mt][nt][2] * alpha, v3 = acc[mt][nt][3] * alpha;
            const size_t o0 = (size_t)z * sC + (size_t)row * N + col;
            const size_t o1 = (size_t)z * sC + (size_t)(row + 8) * N + col;
            if (EPI == 0) {
                Cf[o0] = v0; Cf[o0 + 1] = v1;
                Cf[o1] = v2; Cf[o1 + 1] = v3;
            } else {
                *reinterpret_cast<uint32_t*>(Ch + o0) =
                    pack2(__float2half_rn(v0), __float2half_rn(v1));
                *reinterpret_cast<uint32_t*>(Ch + o1) =
                    pack2(__float2half_rn(v2), __float2half_rn(v3));
            }
        }
    }
}

// ---------------- conversion (x + 3 W fused) / softmax ----------------
__global__ __launch_bounds__(256) void convert_all_kernel(
    const float* __restrict__ x, const float* __restrict__ W0,
    const float* __restrict__ W1, const float* __restrict__ W2,
    h16* __restrict__ x16, h16* __restrict__ w16)
{
    const int zz = blockIdx.z;
    const float* in;
    h16* out;
    size_t n4;
    if (zz == 0) { in = x;  out = x16;                          n4 = (size_t)XR * DD / 4; }
    else {
        in  = (zz == 1) ? W0 : (zz == 2) ? W1 : W2;
        out = w16 + (size_t)(zz - 1) * DD * DD;
        n4  = (size_t)DD * DD / 4;
    }
    for (size_t i = (size_t)blockIdx.x * 256 + threadIdx.x; i < n4; i += (size_t)gridDim.x * 256) {
        const float4 v = reinterpret_cast<const float4*>(in)[i];
        uint2 o;
        o.x = pack2(__float2half_rn(v.x), __float2half_rn(v.y));
        o.y = pack2(__float2half_rn(v.z), __float2half_rn(v.w));
        reinterpret_cast<uint2*>(out)[i] = o;
    }
}

__global__ __launch_bounds__(256) void softmax_kernel(
    const float* __restrict__ P, h16* __restrict__ Ph)
{
    const int row = blockIdx.x & (SS - 1);
    const int b   = blockIdx.x >> 11;
    const size_t base = ((size_t)b * SS + row) * SS;
    const int L = row + 1;
    const int tid = threadIdx.x;

    float v[8];
    float m = -INFINITY;
#pragma unroll
    for (int j = 0; j < 8; j++) {
        const int i = tid + j * 256;
        v[j] = (i < L) ? P[base + i] : -INFINITY;
        m = fmaxf(m, v[j]);
    }
    __shared__ float red[256];
    red[tid] = m; __syncthreads();
    for (int s2 = 128; s2 > 0; s2 >>= 1) {
        if (tid < s2) red[tid] = fmaxf(red[tid], red[tid + s2]);
        __syncthreads();
    }
    m = red[0]; __syncthreads();

    float sum = 0.0f;
#pragma unroll
    for (int j = 0; j < 8; j++) {
        const int i = tid + j * 256;
        if (i < L) { v[j] = __expf(v[j] - m); sum += v[j]; }
    }
    red[tid] = sum; __syncthreads();
    for (int s2 = 128; s2 > 0; s2 >>= 1) {
        if (tid < s2) red[tid] += red[tid + s2];
        __syncthreads();
    }
    const float inv = 1.0f / red[0];
    __syncthreads();

#pragma unroll
    for (int j = 0; j < 8; j++) {
        const int i = tid + j * 256;
        if (i < L) Ph[base + i] = __float2half_rn(v[j] * inv);
    }
    const h16 z16 = __ushort_as_half(0);
    for (int i = L + tid; i < SS; i += 256) Ph[base + i] = z16;
}

// ---------------- launch ----------------
extern "C" void kernel_launch(void* const* d_in, const int* in_sizes, int n_in,
                              void* d_out, int out_size)
{
    const float* x  = (const float*)d_in[0];
    const float* Wq = (const float*)d_in[1];
    const float* Wk = (const float*)d_in[2];
    const float* Wv = (const float*)d_in[3];
    float* out = (float*)d_out;

    h16 *x16, *w16, *QKV, *Ph;
    float* P;
    cudaGetSymbolAddress((void**)&x16, g_x16);
    cudaGetSymbolAddress((void**)&w16, g_w16);
    cudaGetSymbolAddress((void**)&QKV, g_QKV);
    cudaGetSymbolAddress((void**)&P,   g_P);
    cudaGetSymbolAddress((void**)&Ph,  g_Ph);

    cudaFuncSetAttribute(gemm_f16<1,0,1>, cudaFuncAttributeMaxDynamicSharedMemorySize, SMEM_G);
    cudaFuncSetAttribute(gemm_f16<0,1,0>, cudaFuncAttributeMaxDynamicSharedMemorySize, SMEM_G);
    cudaFuncSetAttribute(gemm_f16<0,2,1>, cudaFuncAttributeMaxDynamicSharedMemorySize, SMEM_G);

    const size_t WSZ = (size_t)DD * DD;
    const size_t QSZ = (size_t)XR * DD;

    // fp32 -> fp16 conversions (x and W in natural layouts)
    convert_all_kernel<<<dim3(2048, 1, 4), 256>>>(x, Wq, Wk, Wv, x16, w16);

    // QKV (fused z=3): A = x16 [M,K]; B = w16 [K,N] via trans-ldmatrix
    dim3 g1(DD/128, XR/128, 3);
    gemm_f16<1,0,1><<<g1, 256, SMEM_G>>>(x16, w16, nullptr, QKV,
                                         XR, DD, DD, 0, WSZ, QSZ, 1.0f);

    // scores: P[b] = scale * Q[b] @ K[b]^T  (K is [N,K] natural; causal skip)
    dim3 g2(SS/128, SS/128, BB);
    const float scale = 1.0f / sqrtf((float)DD);
    gemm_f16<0,1,0><<<g2, 256, SMEM_G>>>(QKV, QKV + QSZ, P, nullptr,
                                         SS, SS, DD, (size_t)SS*DD, (size_t)SS*DD,
                                         (size_t)SS*SS, scale);

    // causal softmax -> fp16 P
    softmax_kernel<<<BB * SS, 256>>>(P, Ph);

    // out[b] = P[b] @ V[b]: A = Ph [M,K]; B = V [K,N] natural via trans-ldmatrix
    dim3 g3(DD/128, SS/128, BB);
    gemm_f16<0,2,1><<<g3, 256, SMEM_G>>>(Ph, QKV + 2*QSZ, out, nullptr,
                                         SS, DD, SS, (size_t)SS*SS, (size_t)SS*DD,
                                         (size_t)SS*DD, 1.0f);
}